// round 6
// baseline (speedup 1.0000x reference)
#include <cuda_runtime.h>
#include <cuda_bf16.h>
#include <math.h>
#include <stdint.h>

// ---------------- problem constants ----------------
#define BATCH   4
#define SEQ     8192
#define DM      1024
#define DR      1024
#define DR3     3072
#define CHUNK   64
#define NCHUNK  128
#define MROWS   32768

// ---------------- scratch pool (bytes) ----------------
#define OFF_AIV   ((size_t)0)            // fp32 [MROWS][DR3]
#define OFF_HHI   ((size_t)0)            // bf16 [MROWS][DR] (reuses aiv)
#define OFF_HLO   ((size_t)67108864)
#define OFF_XHI   ((size_t)402653184)
#define OFF_XLO   ((size_t)469762048)
#define OFF_INTRA ((size_t)536870912)
#define OFF_CD    ((size_t)671088640)
#define OFF_S     ((size_t)805306368)
#define OFF_D     ((size_t)807403520)
#define OFF_INC   ((size_t)809500672)
#define OFF_WAHI  ((size_t)811597824)
#define OFF_WALO  ((size_t)817889280)
#define OFF_WMHI  ((size_t)824180736)
#define OFF_WMLO  ((size_t)826277888)
#define POOL_BYTES ((size_t)828375040)

__device__ __align__(1024) char g_pool[POOL_BYTES];

// ---------------- helpers ----------------
__device__ __forceinline__ uint32_t s2u(const void* p) {
    uint32_t a;
    asm("{ .reg .u64 t; cvta.to.shared.u64 t, %1; cvt.u32.u64 %0, t; }" : "=r"(a) : "l"(p));
    return a;
}
__device__ __forceinline__ void cp16(uint32_t dst, const void* src) {
    asm volatile("cp.async.cg.shared.global [%0], [%1], 16;" :: "r"(dst), "l"(src));
}
#define LDSM4(r, addr) \
    asm volatile("ldmatrix.sync.aligned.m8n8.x4.shared.b16 {%0,%1,%2,%3}, [%4];" \
        : "=r"((r)[0]), "=r"((r)[1]), "=r"((r)[2]), "=r"((r)[3]) : "r"(addr))
#define MMA_BF16(d, a, b) \
    asm volatile("mma.sync.aligned.m16n8k16.row.col.f32.bf16.bf16.f32 " \
        "{%0,%1,%2,%3}, {%4,%5,%6,%7}, {%8,%9}, {%0,%1,%2,%3};" \
        : "+f"((d)[0]), "+f"((d)[1]), "+f"((d)[2]), "+f"((d)[3]) \
        : "r"((a)[0]), "r"((a)[1]), "r"((a)[2]), "r"((a)[3]), "r"((b)[0]), "r"((b)[1]))

// ---------------- bf16 3-term GEMM, 128x256 CTA tile, 512 threads ----------------
// C[M,N] = (Ahi+Alo)[M,K] @ (Bhi+Blo)^T  (B stored [N][K], K contiguous)
#define GBM 128
#define GBN 256
#define GBK 32
#define NSTAGE 4
#define STG 49152u   // Ahi 8K | Alo 8K | Bhi 16K | Blo 16K
#define GTHREADS 512

__device__ __forceinline__ void gemm_load_stage(
    int buf, int kt, int NS, uint32_t sb,
    const __nv_bfloat16* Ahi, const __nv_bfloat16* Alo,
    const __nv_bfloat16* Bhi, const __nv_bfloat16* Blo,
    size_t m0, size_t n0, int K, int tid)
{
    if (kt < NS) {
        uint32_t base = sb + (uint32_t)buf * STG;
        size_t kbase = (size_t)kt * GBK;
#pragma unroll
        for (int i = 0; i < 6; i++) {
            int c = tid + i * GTHREADS;             // 0..3071, region uniform per i
            if (c < 1024) {                         // A: hi then lo, 128 rows x 4 chunks
                int hl  = c >> 9;
                int row = (c >> 2) & 127;
                int ch  = c & 3;
                int sw  = ch ^ ((row >> 1) & 3);
                const __nv_bfloat16* src =
                    (hl ? Alo : Ahi) + (m0 + row) * (size_t)K + kbase + ch * 8;
                cp16(base + (uint32_t)hl * 8192u + (uint32_t)(row * 64 + sw * 16), src);
            } else {                                // B: hi then lo, 256 rows x 4 chunks
                int cb  = c - 1024;
                int hl  = cb >> 10;
                int row = (cb >> 2) & 255;
                int ch  = cb & 3;
                int sw  = ch ^ ((row >> 1) & 3);
                const __nv_bfloat16* src =
                    (hl ? Blo : Bhi) + (n0 + row) * (size_t)K + kbase + ch * 8;
                cp16(base + 16384u + (uint32_t)hl * 16384u + (uint32_t)(row * 64 + sw * 16), src);
            }
        }
    }
    asm volatile("cp.async.commit_group;" ::: "memory");
}

__global__ __launch_bounds__(GTHREADS, 1)
void gemm_bf16_kernel(const __nv_bfloat16* __restrict__ Ahi, const __nv_bfloat16* __restrict__ Alo,
                      const __nv_bfloat16* __restrict__ Bhi, const __nv_bfloat16* __restrict__ Blo,
                      const float* __restrict__ bias, float* __restrict__ C,
                      int M, int N, int K, int hasBias)
{
    extern __shared__ __align__(1024) char smem[];
    uint32_t sb = s2u(smem);
    int tid = threadIdx.x, lane = tid & 31, wid = tid >> 5;
    int wm = wid & 3, wn = wid >> 2;               // 4 x 4 warp grid, 32x64 warp tile
    size_t m0 = (size_t)blockIdx.y * GBM;
    size_t n0 = (size_t)blockIdx.x * GBN;
    const int NS = K / GBK;

    float acc[2][8][4];
#pragma unroll
    for (int mt = 0; mt < 2; mt++)
#pragma unroll
        for (int nt = 0; nt < 8; nt++)
#pragma unroll
            for (int j = 0; j < 4; j++) acc[mt][nt][j] = 0.f;

    gemm_load_stage(0, 0, NS, sb, Ahi, Alo, Bhi, Blo, m0, n0, K, tid);
    gemm_load_stage(1, 1, NS, sb, Ahi, Alo, Bhi, Blo, m0, n0, K, tid);
    gemm_load_stage(2, 2, NS, sb, Ahi, Alo, Bhi, Blo, m0, n0, K, tid);

    int arow_b = wm * 32 + (lane & 15);            // + mt*16
    int achb   = lane >> 4;                        // + 2*ks
    int brow_b = wn * 64 + (lane & 7) + ((lane >> 4) & 1) * 8;   // + np*16
    int bchb   = (lane >> 3) & 1;                  // + 2*ks

    for (int s = 0; s < NS; s++) {
        asm volatile("cp.async.wait_group %0;" :: "n"(NSTAGE - 2));
        __syncthreads();
        gemm_load_stage((s + 3) & 3, s + 3, NS, sb, Ahi, Alo, Bhi, Blo, m0, n0, K, tid);
        uint32_t st = sb + (uint32_t)(s & 3) * STG;
#pragma unroll
        for (int ks = 0; ks < 2; ks++) {
            uint32_t a[2][2][4];                    // [hi/lo][mt]
#pragma unroll
            for (int hl = 0; hl < 2; hl++)
#pragma unroll
                for (int mt = 0; mt < 2; mt++) {
                    int row = arow_b + mt * 16;
                    int ch = achb + 2 * ks;
                    int sw = ch ^ ((row >> 1) & 3);
                    LDSM4(a[hl][mt], st + (uint32_t)hl * 8192u + (uint32_t)(row * 64 + sw * 16));
                }
#pragma unroll
            for (int np = 0; np < 4; np++) {
                int row = brow_b + np * 16;
                int ch = bchb + 2 * ks;
                int sw = ch ^ ((row >> 1) & 3);
                uint32_t bh[4], bl[4];
                LDSM4(bh, st + 16384u + (uint32_t)(row * 64 + sw * 16));
                LDSM4(bl, st + 32768u + (uint32_t)(row * 64 + sw * 16));
#pragma unroll
                for (int mt = 0; mt < 2; mt++) {
#pragma unroll
                    for (int half = 0; half < 2; half++) {
                        float* ac = acc[mt][np * 2 + half];
                        MMA_BF16(ac, a[0][mt], &bh[half * 2]);   // hi*hi
                        MMA_BF16(ac, a[1][mt], &bh[half * 2]);   // lo*hi
                        MMA_BF16(ac, a[0][mt], &bl[half * 2]);   // hi*lo
                    }
                }
            }
        }
    }

    // epilogue
#pragma unroll
    for (int mt = 0; mt < 2; mt++) {
        size_t row = m0 + wm * 32 + mt * 16 + (lane >> 2);
#pragma unroll
        for (int half = 0; half < 2; half++) {
            float* Cp = C + (row + half * 8) * (size_t)N + n0 + wn * 64 + (lane & 3) * 2;
#pragma unroll
            for (int nt = 0; nt < 8; nt++) {
                float2 v;
                v.x = acc[mt][nt][half * 2];
                v.y = acc[mt][nt][half * 2 + 1];
                if (hasBias) {
                    int col = (int)(n0 + wn * 64 + nt * 8 + (lane & 3) * 2);
                    v.x += __ldg(&bias[col]);
                    v.y += __ldg(&bias[col + 1]);
                }
                *(float2*)(Cp + nt * 8) = v;
            }
        }
    }
}

// ---------------- fast exp (FMA pipe) ----------------
__device__ __forceinline__ float fast_exp(float x) {
    float t = x * 1.4426950408889634f;
    t = fminf(fmaxf(t, -126.f), 126.f);
    float z = t + 12582912.f;
    int i = __float_as_int(z);
    float f = t - (z - 12582912.f);
    float p = 1.5403530e-4f;
    p = fmaf(p, f, 1.3333558e-3f);
    p = fmaf(p, f, 9.6181291e-3f);
    p = fmaf(p, f, 5.5504109e-2f);
    p = fmaf(p, f, 2.4022651e-1f);
    p = fmaf(p, f, 6.9314718e-1f);
    p = fmaf(p, f, 1.0f);
    return __int_as_float(__float_as_int(p) + (i << 23));
}
__device__ __forceinline__ float rcp_approx(float x) {
    float r; asm("rcp.approx.f32 %0, %1;" : "=f"(r) : "f"(x)); return r;
}
__device__ __forceinline__ float sqrt_approx(float x) {
    float r; asm("sqrt.approx.f32 %0, %1;" : "=f"(r) : "f"(x)); return r;
}

// ---------------- gates + within-chunk clamped scan ----------------
__global__ __launch_bounds__(256) void gate_intra_kernel(
    const float* __restrict__ aiv, const float* __restrict__ bias,
    float* __restrict__ intra_out, float* __restrict__ cd_out,
    float* __restrict__ S_out, float* __restrict__ D_out)
{
    int g = blockIdx.x * 256 + threadIdx.x;
    int d = g & (DR - 1);
    int n = (g >> 10) & (NCHUNK - 1);
    int b = g >> 17;

    float bd = bias[d];
    float cd = 1.f, inv_cd = 1.f, wsum = 0.f, intra = 0.f;
    size_t row0 = (size_t)b * SEQ + (size_t)n * CHUNK;

    for (int t = 0; t < CHUNK; t++) {
        size_t row = row0 + t;
        const float* p = aiv + row * DR3;
        float ap  = p[d];
        float ipr = p[d + DR];
        float v   = p[d + 2 * DR];

        float ea = fast_exp(-(ap + bd));
        float ua = 1.f + ea;                 // = 1/a
        float ei = fast_exp(-ipr);
        float ui = 1.f + ei;                 // = 1/i
        float r = rcp_approx(ua * ui);
        float a  = r * ui;
        float ii = r * ua;
        float sig = sqrt_approx(fmaxf(fmaf(-a, a, 1.f), 1e-8f)) * (ii * v);

        cd *= a;
        inv_cd *= ua;
        float w = (cd >= 1e-10f) ? inv_cd : 1e10f;
        wsum = fmaf(sig, w, wsum);
        intra = cd * wsum;

        size_t o = row * DR + d;
        intra_out[o] = intra;
        cd_out[o]    = cd;
    }
    S_out[g] = intra;
    D_out[g] = cd;
}

// ---------------- chunk-level recurrence (reference-exact log/exp path) ----------------
__global__ void chunk_scan_kernel(const float* __restrict__ S, const float* __restrict__ D,
                                  float* __restrict__ inc)
{
    int g = blockIdx.x * blockDim.x + threadIdx.x;
    if (g >= BATCH * DR) return;
    int d = g & (DR - 1);
    int b = g >> 10;

    float cum_log = 0.f, cumW = 0.f;
    float prevP = 1.f, prevW = 0.f;
    size_t base = (size_t)b * NCHUNK * DR + d;

    for (int n = 0; n < NCHUNK; n++) {
        size_t idx = base + (size_t)n * DR;
        inc[idx] = prevP * prevW;
        cum_log += logf(fmaxf(D[idx], 1e-10f));
        float cumP = expf(cum_log);
        cumW += S[idx] / fmaxf(cumP, 1e-10f);
        prevP = cumP;
        prevW = cumW;
    }
}

// ---------------- cross-chunk fixup + bf16 hi/lo split of h ----------------
__global__ __launch_bounds__(256) void apply_cross_split_kernel(
    const float* __restrict__ intra, const float* __restrict__ cd,
    const float* __restrict__ inc,
    __nv_bfloat16* __restrict__ hhi, __nv_bfloat16* __restrict__ hlo)
{
    size_t i4 = (size_t)blockIdx.x * 256 + threadIdx.x;
    size_t base = i4 * 4;
    int d = (int)(base & (DR - 1));
    size_t row = base >> 10;
    int t = (int)(row & (SEQ - 1));
    int b = (int)(row >> 13);
    int n = t >> 6;

    float4 iv = ((const float4*)intra)[i4];
    float4 cv = ((const float4*)cd)[i4];
    float4 nv = *(const float4*)(inc + (((size_t)(b * NCHUNK + n)) << 10) + d);

    float h[4];
    h[0] = fmaf(cv.x, nv.x, iv.x);
    h[1] = fmaf(cv.y, nv.y, iv.y);
    h[2] = fmaf(cv.z, nv.z, iv.z);
    h[3] = fmaf(cv.w, nv.w, iv.w);

    ushort4 sh, sl;
    unsigned short* shp = &sh.x;
    unsigned short* slp = &sl.x;
#pragma unroll
    for (int j = 0; j < 4; j++) {
        __nv_bfloat16 hi = __float2bfloat16_rn(h[j]);
        __nv_bfloat16 lo = __float2bfloat16_rn(h[j] - __bfloat162float(hi));
        shp[j] = __bfloat16_as_ushort(hi);
        slp[j] = __bfloat16_as_ushort(lo);
    }
    ((ushort4*)hhi)[i4] = sh;
    ((ushort4*)hlo)[i4] = sl;
}

// ---------------- split x into bf16 hi/lo ----------------
__global__ __launch_bounds__(256) void split_kernel(const float* __restrict__ x,
                                                    __nv_bfloat16* __restrict__ hi,
                                                    __nv_bfloat16* __restrict__ lo)
{
    size_t i = (size_t)blockIdx.x * 256 + threadIdx.x;
    float4 v = ((const float4*)x)[i];
    float vv[4] = { v.x, v.y, v.z, v.w };
    ushort4 sh, sl;
    unsigned short* shp = &sh.x;
    unsigned short* slp = &sl.x;
#pragma unroll
    for (int j = 0; j < 4; j++) {
        __nv_bfloat16 h = __float2bfloat16_rn(vv[j]);
        __nv_bfloat16 l = __float2bfloat16_rn(vv[j] - __bfloat162float(h));
        shp[j] = __bfloat16_as_ushort(h);
        slp[j] = __bfloat16_as_ushort(l);
    }
    ((ushort4*)hi)[i] = sh;
    ((ushort4*)lo)[i] = sl;
}

// ---------------- transpose W[K][N] -> [N][K], bf16 hi/lo split ----------------
__global__ void transpose_split_kernel(const float* __restrict__ W,
                                       __nv_bfloat16* __restrict__ Thi,
                                       __nv_bfloat16* __restrict__ Tlo,
                                       int K, int N)
{
    __shared__ float tile[32][33];
    int n0 = blockIdx.x * 32, k0 = blockIdx.y * 32;
    int tx = threadIdx.x, ty = threadIdx.y;
#pragma unroll
    for (int i = 0; i < 32; i += 8)
        tile[ty + i][tx] = W[(size_t)(k0 + ty + i) * N + n0 + tx];
    __syncthreads();
#pragma unroll
    for (int i = 0; i < 32; i += 8) {
        float v = tile[tx][ty + i];
        __nv_bfloat16 h = __float2bfloat16_rn(v);
        __nv_bfloat16 l = __float2bfloat16_rn(v - __bfloat162float(h));
        Thi[(size_t)(n0 + ty + i) * K + k0 + tx] = h;
        Tlo[(size_t)(n0 + ty + i) * K + k0 + tx] = l;
    }
}

// ---------------- launch ----------------
extern "C" void kernel_launch(void* const* d_in, const int* in_sizes, int n_in,
                              void* d_out, int out_size)
{
    const float* x          = (const float*)d_in[0];
    const float* W_aiv      = (const float*)d_in[1];
    const float* decay_bias = (const float*)d_in[2];
    const float* W_mix      = (const float*)d_in[3];
    const float* b_mix      = (const float*)d_in[4];
    float* out = (float*)d_out;

    char* pool = nullptr;
    cudaGetSymbolAddress((void**)&pool, g_pool);
    float* aiv            = (float*)(pool + OFF_AIV);
    __nv_bfloat16* hhi    = (__nv_bfloat16*)(pool + OFF_HHI);
    __nv_bfloat16* hlo    = (__nv_bfloat16*)(pool + OFF_HLO);
    __nv_bfloat16* xhi    = (__nv_bfloat16*)(pool + OFF_XHI);
    __nv_bfloat16* xlo    = (__nv_bfloat16*)(pool + OFF_XLO);
    float* intra          = (float*)(pool + OFF_INTRA);
    float* cd             = (float*)(pool + OFF_CD);
    float* Sp             = (float*)(pool + OFF_S);
    float* Dp             = (float*)(pool + OFF_D);
    float* incp           = (float*)(pool + OFF_INC);
    __nv_bfloat16* wahi   = (__nv_bfloat16*)(pool + OFF_WAHI);
    __nv_bfloat16* walo   = (__nv_bfloat16*)(pool + OFF_WALO);
    __nv_bfloat16* wmhi   = (__nv_bfloat16*)(pool + OFF_WMHI);
    __nv_bfloat16* wmlo   = (__nv_bfloat16*)(pool + OFF_WMLO);

    const int smem_bytes = NSTAGE * (int)STG;   // 196608
    cudaFuncSetAttribute(gemm_bf16_kernel,
                         cudaFuncAttributeMaxDynamicSharedMemorySize, smem_bytes);

    // prep bf16 splits
    split_kernel<<<(MROWS * DM / 4) / 256, 256>>>(x, xhi, xlo);
    transpose_split_kernel<<<dim3(DR3 / 32, DM / 32), dim3(32, 8)>>>(W_aiv, wahi, walo, DM, DR3);
    transpose_split_kernel<<<dim3(DR / 32, DR / 32), dim3(32, 8)>>>(W_mix, wmhi, wmlo, DR, DR);

    // 1. aiv = x @ W_aiv
    gemm_bf16_kernel<<<dim3(DR3 / GBN, MROWS / GBM), GTHREADS, smem_bytes>>>(
        xhi, xlo, wahi, walo, nullptr, aiv, MROWS, DR3, DM, 0);

    // 2. gates + within-chunk scan
    gate_intra_kernel<<<(BATCH * NCHUNK * DR) / 256, 256>>>(aiv, decay_bias, intra, cd, Sp, Dp);

    // 3. chunk-level recurrence
    chunk_scan_kernel<<<(BATCH * DR) / 256, 256>>>(Sp, Dp, incp);

    // 4. cross-chunk fixup + bf16 split of h (reuses aiv region)
    apply_cross_split_kernel<<<(unsigned)((size_t)MROWS * DR / 4 / 256), 256>>>(
        intra, cd, incp, hhi, hlo);

    // 5. out = h @ W_mix + b_mix
    gemm_bf16_kernel<<<dim3(DR / GBN, MROWS / GBM), GTHREADS, smem_bytes>>>(
        hhi, hlo, wmhi, wmlo, b_mix, out, MROWS, DR, DR, 1);
}

// round 7
// speedup vs baseline: 1.0033x; 1.0033x over previous
#include <cuda_runtime.h>
#include <cuda_bf16.h>
#include <math.h>
#include <stdint.h>

// ---------------- problem constants ----------------
#define BATCH   4
#define SEQ     8192
#define DM      1024
#define DR      1024
#define DR3     3072
#define CHUNK   64
#define NCHUNK  128
#define MROWS   32768

// ---------------- scratch pool (bytes) ----------------
#define OFF_AIV   ((size_t)0)            // fp32 [MROWS][DR3]
#define OFF_HHI   ((size_t)0)            // bf16 [MROWS][DR] (reuses aiv)
#define OFF_HLO   ((size_t)67108864)
#define OFF_XHI   ((size_t)402653184)
#define OFF_XLO   ((size_t)469762048)
#define OFF_INTRA ((size_t)536870912)
#define OFF_CD    ((size_t)671088640)
#define OFF_S     ((size_t)805306368)
#define OFF_D     ((size_t)807403520)
#define OFF_INC   ((size_t)809500672)
#define OFF_WAHI  ((size_t)811597824)
#define OFF_WALO  ((size_t)817889280)
#define OFF_WMHI  ((size_t)824180736)
#define OFF_WMLO  ((size_t)826277888)
#define POOL_BYTES ((size_t)828375040)

__device__ __align__(1024) char g_pool[POOL_BYTES];

// ---------------- helpers ----------------
__device__ __forceinline__ uint32_t s2u(const void* p) {
    uint32_t a;
    asm("{ .reg .u64 t; cvta.to.shared.u64 t, %1; cvt.u32.u64 %0, t; }" : "=r"(a) : "l"(p));
    return a;
}
__device__ __forceinline__ void cp16(uint32_t dst, const void* src) {
    asm volatile("cp.async.cg.shared.global [%0], [%1], 16;" :: "r"(dst), "l"(src));
}
#define LDSM4(r, addr) \
    asm volatile("ldmatrix.sync.aligned.m8n8.x4.shared.b16 {%0,%1,%2,%3}, [%4];" \
        : "=r"((r)[0]), "=r"((r)[1]), "=r"((r)[2]), "=r"((r)[3]) : "r"(addr))
#define MMA_BF16(d, a, b) \
    asm volatile("mma.sync.aligned.m16n8k16.row.col.f32.bf16.bf16.f32 " \
        "{%0,%1,%2,%3}, {%4,%5,%6,%7}, {%8,%9}, {%0,%1,%2,%3};" \
        : "+f"((d)[0]), "+f"((d)[1]), "+f"((d)[2]), "+f"((d)[3]) \
        : "r"((a)[0]), "r"((a)[1]), "r"((a)[2]), "r"((a)[3]), "r"((b)[0]), "r"((b)[1]))

// ---------------- bf16 3-term GEMM, 128x256 CTA tile, 256 threads ----------------
// C[M,N] = (Ahi+Alo)[M,K] @ (Bhi+Blo)^T  (B stored [N][K], K contiguous)
#define GBM 128
#define GBN 256
#define GBK 32
#define NSTAGE 4
#define STG 49152u   // Ahi 8K | Alo 8K | Bhi 16K | Blo 16K

__device__ __forceinline__ void gemm_load_stage(
    int buf, int kt, int NS, uint32_t sb,
    const __nv_bfloat16* Ahi, const __nv_bfloat16* Alo,
    const __nv_bfloat16* Bhi, const __nv_bfloat16* Blo,
    size_t m0, size_t n0, int K, int tid)
{
    if (kt < NS) {
        uint32_t base = sb + (uint32_t)buf * STG;
        size_t kbase = (size_t)kt * GBK;
#pragma unroll
        for (int i = 0; i < 12; i++) {
            int c = tid + i * 256;                  // 0..3071, region uniform per i
            if (c < 1024) {                         // A: hi then lo, 128 rows x 4 chunks
                int hl  = c >> 9;
                int row = (c >> 2) & 127;
                int ch  = c & 3;
                int sw  = ch ^ ((row >> 1) & 3);
                const __nv_bfloat16* src =
                    (hl ? Alo : Ahi) + (m0 + row) * (size_t)K + kbase + ch * 8;
                cp16(base + (uint32_t)hl * 8192u + (uint32_t)(row * 64 + sw * 16), src);
            } else {                                // B: hi then lo, 256 rows x 4 chunks
                int cb  = c - 1024;
                int hl  = cb >> 10;
                int row = (cb >> 2) & 255;
                int ch  = cb & 3;
                int sw  = ch ^ ((row >> 1) & 3);
                const __nv_bfloat16* src =
                    (hl ? Blo : Bhi) + (n0 + row) * (size_t)K + kbase + ch * 8;
                cp16(base + 16384u + (uint32_t)hl * 16384u + (uint32_t)(row * 64 + sw * 16), src);
            }
        }
    }
    asm volatile("cp.async.commit_group;" ::: "memory");
}

__global__ __launch_bounds__(256, 1)
void gemm_bf16_kernel(const __nv_bfloat16* __restrict__ Ahi, const __nv_bfloat16* __restrict__ Alo,
                      const __nv_bfloat16* __restrict__ Bhi, const __nv_bfloat16* __restrict__ Blo,
                      const float* __restrict__ bias, float* __restrict__ C,
                      int M, int N, int K, int hasBias)
{
    extern __shared__ __align__(1024) char smem[];
    uint32_t sb = s2u(smem);
    int tid = threadIdx.x, lane = tid & 31, wid = tid >> 5;
    int wm = wid & 1, wn = wid >> 1;               // 2 x 4 warp grid, 64x64 warp tile
    size_t m0 = (size_t)blockIdx.y * GBM;
    size_t n0 = (size_t)blockIdx.x * GBN;
    const int NS = K / GBK;

    float acc[4][8][4];
#pragma unroll
    for (int mt = 0; mt < 4; mt++)
#pragma unroll
        for (int nt = 0; nt < 8; nt++)
#pragma unroll
            for (int j = 0; j < 4; j++) acc[mt][nt][j] = 0.f;

    gemm_load_stage(0, 0, NS, sb, Ahi, Alo, Bhi, Blo, m0, n0, K, tid);
    gemm_load_stage(1, 1, NS, sb, Ahi, Alo, Bhi, Blo, m0, n0, K, tid);
    gemm_load_stage(2, 2, NS, sb, Ahi, Alo, Bhi, Blo, m0, n0, K, tid);

    int arow_b = wm * 64 + (lane & 15);            // + mt*16
    int achb   = lane >> 4;                        // + 2*ks
    int brow_b = wn * 64 + (lane & 7) + ((lane >> 4) & 1) * 8;   // + np*16
    int bchb   = (lane >> 3) & 1;                  // + 2*ks

    for (int s = 0; s < NS; s++) {
        asm volatile("cp.async.wait_group %0;" :: "n"(NSTAGE - 2));
        __syncthreads();
        gemm_load_stage((s + 3) & 3, s + 3, NS, sb, Ahi, Alo, Bhi, Blo, m0, n0, K, tid);
        uint32_t st = sb + (uint32_t)(s & 3) * STG;
#pragma unroll
        for (int ks = 0; ks < 2; ks++) {
            uint32_t a[2][4][4];                    // [hi/lo][mt]
#pragma unroll
            for (int hl = 0; hl < 2; hl++)
#pragma unroll
                for (int mt = 0; mt < 4; mt++) {
                    int row = arow_b + mt * 16;
                    int ch = achb + 2 * ks;
                    int sw = ch ^ ((row >> 1) & 3);
                    LDSM4(a[hl][mt], st + (uint32_t)hl * 8192u + (uint32_t)(row * 64 + sw * 16));
                }
#pragma unroll
            for (int np = 0; np < 4; np++) {
                int row = brow_b + np * 16;
                int ch = bchb + 2 * ks;
                int sw = ch ^ ((row >> 1) & 3);
                uint32_t bh[4], bl[4];
                LDSM4(bh, st + 16384u + (uint32_t)(row * 64 + sw * 16));
                LDSM4(bl, st + 32768u + (uint32_t)(row * 64 + sw * 16));
                // term-outer ordering: same-accumulator reuse distance = 8 MMAs
#pragma unroll
                for (int term = 0; term < 3; term++) {
                    uint32_t (*aT)[4] = (term == 1) ? a[1] : a[0];   // lo only for term 1
                    uint32_t* bT = (term == 2) ? bl : bh;            // lo only for term 2
#pragma unroll
                    for (int mt = 0; mt < 4; mt++) {
#pragma unroll
                        for (int half = 0; half < 2; half++) {
                            MMA_BF16(acc[mt][np * 2 + half], aT[mt], &bT[half * 2]);
                        }
                    }
                }
            }
        }
    }

    // epilogue
#pragma unroll
    for (int mt = 0; mt < 4; mt++) {
        size_t row = m0 + wm * 64 + mt * 16 + (lane >> 2);
#pragma unroll
        for (int half = 0; half < 2; half++) {
            float* Cp = C + (row + half * 8) * (size_t)N + n0 + wn * 64 + (lane & 3) * 2;
#pragma unroll
            for (int nt = 0; nt < 8; nt++) {
                float2 v;
                v.x = acc[mt][nt][half * 2];
                v.y = acc[mt][nt][half * 2 + 1];
                if (hasBias) {
                    int col = (int)(n0 + wn * 64 + nt * 8 + (lane & 3) * 2);
                    v.x += __ldg(&bias[col]);
                    v.y += __ldg(&bias[col + 1]);
                }
                *(float2*)(Cp + nt * 8) = v;
            }
        }
    }
}

// ---------------- fast exp (FMA pipe) ----------------
__device__ __forceinline__ float fast_exp(float x) {
    float t = x * 1.4426950408889634f;
    t = fminf(fmaxf(t, -126.f), 126.f);
    float z = t + 12582912.f;
    int i = __float_as_int(z);
    float f = t - (z - 12582912.f);
    float p = 1.5403530e-4f;
    p = fmaf(p, f, 1.3333558e-3f);
    p = fmaf(p, f, 9.6181291e-3f);
    p = fmaf(p, f, 5.5504109e-2f);
    p = fmaf(p, f, 2.4022651e-1f);
    p = fmaf(p, f, 6.9314718e-1f);
    p = fmaf(p, f, 1.0f);
    return __int_as_float(__float_as_int(p) + (i << 23));
}
__device__ __forceinline__ float rcp_approx(float x) {
    float r; asm("rcp.approx.f32 %0, %1;" : "=f"(r) : "f"(x)); return r;
}
__device__ __forceinline__ float sqrt_approx(float x) {
    float r; asm("sqrt.approx.f32 %0, %1;" : "=f"(r) : "f"(x)); return r;
}

// ---------------- gates + within-chunk clamped scan ----------------
__global__ __launch_bounds__(256) void gate_intra_kernel(
    const float* __restrict__ aiv, const float* __restrict__ bias,
    float* __restrict__ intra_out, float* __restrict__ cd_out,
    float* __restrict__ S_out, float* __restrict__ D_out)
{
    int g = blockIdx.x * 256 + threadIdx.x;
    int d = g & (DR - 1);
    int n = (g >> 10) & (NCHUNK - 1);
    int b = g >> 17;

    float bd = bias[d];
    float cd = 1.f, inv_cd = 1.f, wsum = 0.f, intra = 0.f;
    size_t row0 = (size_t)b * SEQ + (size_t)n * CHUNK;

    for (int t = 0; t < CHUNK; t++) {
        size_t row = row0 + t;
        const float* p = aiv + row * DR3;
        float ap  = p[d];
        float ipr = p[d + DR];
        float v   = p[d + 2 * DR];

        float ea = fast_exp(-(ap + bd));
        float ua = 1.f + ea;                 // = 1/a
        float ei = fast_exp(-ipr);
        float ui = 1.f + ei;                 // = 1/i
        float r = rcp_approx(ua * ui);
        float a  = r * ui;
        float ii = r * ua;
        float sig = sqrt_approx(fmaxf(fmaf(-a, a, 1.f), 1e-8f)) * (ii * v);

        cd *= a;
        inv_cd *= ua;
        float w = (cd >= 1e-10f) ? inv_cd : 1e10f;
        wsum = fmaf(sig, w, wsum);
        intra = cd * wsum;

        size_t o = row * DR + d;
        intra_out[o] = intra;
        cd_out[o]    = cd;
    }
    S_out[g] = intra;
    D_out[g] = cd;
}

// ---------------- chunk-level recurrence (reference-exact log/exp path) ----------------
__global__ void chunk_scan_kernel(const float* __restrict__ S, const float* __restrict__ D,
                                  float* __restrict__ inc)
{
    int g = blockIdx.x * blockDim.x + threadIdx.x;
    if (g >= BATCH * DR) return;
    int d = g & (DR - 1);
    int b = g >> 10;

    float cum_log = 0.f, cumW = 0.f;
    float prevP = 1.f, prevW = 0.f;
    size_t base = (size_t)b * NCHUNK * DR + d;

    for (int n = 0; n < NCHUNK; n++) {
        size_t idx = base + (size_t)n * DR;
        inc[idx] = prevP * prevW;
        cum_log += logf(fmaxf(D[idx], 1e-10f));
        float cumP = expf(cum_log);
        cumW += S[idx] / fmaxf(cumP, 1e-10f);
        prevP = cumP;
        prevW = cumW;
    }
}

// ---------------- cross-chunk fixup + bf16 hi/lo split of h ----------------
__global__ __launch_bounds__(256) void apply_cross_split_kernel(
    const float* __restrict__ intra, const float* __restrict__ cd,
    const float* __restrict__ inc,
    __nv_bfloat16* __restrict__ hhi, __nv_bfloat16* __restrict__ hlo)
{
    size_t i4 = (size_t)blockIdx.x * 256 + threadIdx.x;
    size_t base = i4 * 4;
    int d = (int)(base & (DR - 1));
    size_t row = base >> 10;
    int t = (int)(row & (SEQ - 1));
    int b = (int)(row >> 13);
    int n = t >> 6;

    float4 iv = ((const float4*)intra)[i4];
    float4 cv = ((const float4*)cd)[i4];
    float4 nv = *(const float4*)(inc + (((size_t)(b * NCHUNK + n)) << 10) + d);

    float h[4];
    h[0] = fmaf(cv.x, nv.x, iv.x);
    h[1] = fmaf(cv.y, nv.y, iv.y);
    h[2] = fmaf(cv.z, nv.z, iv.z);
    h[3] = fmaf(cv.w, nv.w, iv.w);

    ushort4 sh, sl;
    unsigned short* shp = &sh.x;
    unsigned short* slp = &sl.x;
#pragma unroll
    for (int j = 0; j < 4; j++) {
        __nv_bfloat16 hi = __float2bfloat16_rn(h[j]);
        __nv_bfloat16 lo = __float2bfloat16_rn(h[j] - __bfloat162float(hi));
        shp[j] = __bfloat16_as_ushort(hi);
        slp[j] = __bfloat16_as_ushort(lo);
    }
    ((ushort4*)hhi)[i4] = sh;
    ((ushort4*)hlo)[i4] = sl;
}

// ---------------- split x into bf16 hi/lo ----------------
__global__ __launch_bounds__(256) void split_kernel(const float* __restrict__ x,
                                                    __nv_bfloat16* __restrict__ hi,
                                                    __nv_bfloat16* __restrict__ lo)
{
    size_t i = (size_t)blockIdx.x * 256 + threadIdx.x;
    float4 v = ((const float4*)x)[i];
    float vv[4] = { v.x, v.y, v.z, v.w };
    ushort4 sh, sl;
    unsigned short* shp = &sh.x;
    unsigned short* slp = &sl.x;
#pragma unroll
    for (int j = 0; j < 4; j++) {
        __nv_bfloat16 h = __float2bfloat16_rn(vv[j]);
        __nv_bfloat16 l = __float2bfloat16_rn(vv[j] - __bfloat162float(h));
        shp[j] = __bfloat16_as_ushort(h);
        slp[j] = __bfloat16_as_ushort(l);
    }
    ((ushort4*)hi)[i] = sh;
    ((ushort4*)lo)[i] = sl;
}

// ---------------- transpose W[K][N] -> [N][K], bf16 hi/lo split ----------------
__global__ void transpose_split_kernel(const float* __restrict__ W,
                                       __nv_bfloat16* __restrict__ Thi,
                                       __nv_bfloat16* __restrict__ Tlo,
                                       int K, int N)
{
    __shared__ float tile[32][33];
    int n0 = blockIdx.x * 32, k0 = blockIdx.y * 32;
    int tx = threadIdx.x, ty = threadIdx.y;
#pragma unroll
    for (int i = 0; i < 32; i += 8)
        tile[ty + i][tx] = W[(size_t)(k0 + ty + i) * N + n0 + tx];
    __syncthreads();
#pragma unroll
    for (int i = 0; i < 32; i += 8) {
        float v = tile[tx][ty + i];
        __nv_bfloat16 h = __float2bfloat16_rn(v);
        __nv_bfloat16 l = __float2bfloat16_rn(v - __bfloat162float(h));
        Thi[(size_t)(n0 + ty + i) * K + k0 + tx] = h;
        Tlo[(size_t)(n0 + ty + i) * K + k0 + tx] = l;
    }
}

// ---------------- launch ----------------
extern "C" void kernel_launch(void* const* d_in, const int* in_sizes, int n_in,
                              void* d_out, int out_size)
{
    const float* x          = (const float*)d_in[0];
    const float* W_aiv      = (const float*)d_in[1];
    const float* decay_bias = (const float*)d_in[2];
    const float* W_mix      = (const float*)d_in[3];
    const float* b_mix      = (const float*)d_in[4];
    float* out = (float*)d_out;

    char* pool = nullptr;
    cudaGetSymbolAddress((void**)&pool, g_pool);
    float* aiv            = (float*)(pool + OFF_AIV);
    __nv_bfloat16* hhi    = (__nv_bfloat16*)(pool + OFF_HHI);
    __nv_bfloat16* hlo    = (__nv_bfloat16*)(pool + OFF_HLO);
    __nv_bfloat16* xhi    = (__nv_bfloat16*)(pool + OFF_XHI);
    __nv_bfloat16* xlo    = (__nv_bfloat16*)(pool + OFF_XLO);
    float* intra          = (float*)(pool + OFF_INTRA);
    float* cd             = (float*)(pool + OFF_CD);
    float* Sp             = (float*)(pool + OFF_S);
    float* Dp             = (float*)(pool + OFF_D);
    float* incp           = (float*)(pool + OFF_INC);
    __nv_bfloat16* wahi   = (__nv_bfloat16*)(pool + OFF_WAHI);
    __nv_bfloat16* walo   = (__nv_bfloat16*)(pool + OFF_WALO);
    __nv_bfloat16* wmhi   = (__nv_bfloat16*)(pool + OFF_WMHI);
    __nv_bfloat16* wmlo   = (__nv_bfloat16*)(pool + OFF_WMLO);

    const int smem_bytes = NSTAGE * (int)STG;   // 196608
    cudaFuncSetAttribute(gemm_bf16_kernel,
                         cudaFuncAttributeMaxDynamicSharedMemorySize, smem_bytes);

    // prep bf16 splits
    split_kernel<<<(MROWS * DM / 4) / 256, 256>>>(x, xhi, xlo);
    transpose_split_kernel<<<dim3(DR3 / 32, DM / 32), dim3(32, 8)>>>(W_aiv, wahi, walo, DM, DR3);
    transpose_split_kernel<<<dim3(DR / 32, DR / 32), dim3(32, 8)>>>(W_mix, wmhi, wmlo, DR, DR);

    // 1. aiv = x @ W_aiv
    gemm_bf16_kernel<<<dim3(DR3 / GBN, MROWS / GBM), 256, smem_bytes>>>(
        xhi, xlo, wahi, walo, nullptr, aiv, MROWS, DR3, DM, 0);

    // 2. gates + within-chunk scan
    gate_intra_kernel<<<(BATCH * NCHUNK * DR) / 256, 256>>>(aiv, decay_bias, intra, cd, Sp, Dp);

    // 3. chunk-level recurrence
    chunk_scan_kernel<<<(BATCH * DR) / 256, 256>>>(Sp, Dp, incp);

    // 4. cross-chunk fixup + bf16 split of h (reuses aiv region)
    apply_cross_split_kernel<<<(unsigned)((size_t)MROWS * DR / 4 / 256), 256>>>(
        intra, cd, incp, hhi, hlo);

    // 5. out = h @ W_mix + b_mix
    gemm_bf16_kernel<<<dim3(DR / GBN, MROWS / GBM), 256, smem_bytes>>>(
        hhi, hlo, wmhi, wmlo, b_mix, out, MROWS, DR, DR, 1);
}

// round 9
// speedup vs baseline: 1.3190x; 1.3146x over previous
#include <cuda_runtime.h>
#include <cuda_fp16.h>
#include <math.h>
#include <stdint.h>

// ---------------- problem constants ----------------
#define BATCH   4
#define SEQ     8192
#define DM      1024
#define DR      1024
#define DR3     3072
#define CHUNK   64
#define NCHUNK  128
#define MROWS   32768

// ---------------- scratch pool (bytes) ----------------
#define OFF_AIV   ((size_t)0)            // fp32 [MROWS][DR3]
#define OFF_HHI   ((size_t)0)            // fp16 [MROWS][DR] (reuses aiv)
#define OFF_HLO   ((size_t)67108864)
#define OFF_XHI   ((size_t)402653184)    // fp16 [MROWS][DM]
#define OFF_XLO   ((size_t)469762048)
#define OFF_INTRA ((size_t)536870912)
#define OFF_CD    ((size_t)671088640)
#define OFF_S     ((size_t)805306368)
#define OFF_D     ((size_t)807403520)
#define OFF_INC   ((size_t)809500672)
#define OFF_WA    ((size_t)811597824)    // fp16 [DR3][DM] transposed
#define OFF_WM    ((size_t)824180736)    // fp16 [DR][DR] transposed
#define POOL_BYTES ((size_t)828375040)

__device__ __align__(1024) char g_pool[POOL_BYTES];

// ---------------- helpers ----------------
__device__ __forceinline__ uint32_t s2u(const void* p) {
    uint32_t a;
    asm("{ .reg .u64 t; cvta.to.shared.u64 t, %1; cvt.u32.u64 %0, t; }" : "=r"(a) : "l"(p));
    return a;
}
__device__ __forceinline__ void cp16(uint32_t dst, const void* src) {
    asm volatile("cp.async.cg.shared.global [%0], [%1], 16;" :: "r"(dst), "l"(src));
}
#define LDSM4(r, addr) \
    asm volatile("ldmatrix.sync.aligned.m8n8.x4.shared.b16 {%0,%1,%2,%3}, [%4];" \
        : "=r"((r)[0]), "=r"((r)[1]), "=r"((r)[2]), "=r"((r)[3]) : "r"(addr))
#define MMA_F16(d, a, b) \
    asm volatile("mma.sync.aligned.m16n8k16.row.col.f32.f16.f16.f32 " \
        "{%0,%1,%2,%3}, {%4,%5,%6,%7}, {%8,%9}, {%0,%1,%2,%3};" \
        : "+f"((d)[0]), "+f"((d)[1]), "+f"((d)[2]), "+f"((d)[3]) \
        : "r"((a)[0]), "r"((a)[1]), "r"((a)[2]), "r"((a)[3]), "r"((b)[0]), "r"((b)[1]))

// ---------------- fp16 2-term GEMM, 128x256 CTA tile, 256 threads ----------------
// C[M,N] = (Ahi+Alo)[M,K] @ B^T  (B stored [N][K] fp16, K contiguous)
#define GBM 128
#define GBN 256
#define GBK 32
#define NSTAGE 4
#define STG 32768u   // Ahi 8K | Alo 8K | B 16K

__device__ __forceinline__ void gemm_load_stage(
    int buf, int kt, int NS, uint32_t sb,
    const __half* Ahi, const __half* Alo, const __half* B,
    size_t m0, size_t n0, int K, int tid)
{
    if (kt < NS) {
        uint32_t base = sb + (uint32_t)buf * STG;
        size_t kbase = (size_t)kt * GBK;
#pragma unroll
        for (int i = 0; i < 8; i++) {
            int c = tid + i * 256;                  // 0..2047, region uniform per i
            if (c < 1024) {                         // A: hi then lo, 128 rows x 4 chunks
                int hl  = c >> 9;
                int row = (c >> 2) & 127;
                int ch  = c & 3;
                int sw  = ch ^ ((row >> 1) & 3);
                const __half* src =
                    (hl ? Alo : Ahi) + (m0 + row) * (size_t)K + kbase + ch * 8;
                cp16(base + (uint32_t)hl * 8192u + (uint32_t)(row * 64 + sw * 16), src);
            } else {                                // B: 256 rows x 4 chunks
                int cb  = c - 1024;
                int row = cb >> 2;
                int ch  = cb & 3;
                int sw  = ch ^ ((row >> 1) & 3);
                const __half* src = B + (n0 + row) * (size_t)K + kbase + ch * 8;
                cp16(base + 16384u + (uint32_t)(row * 64 + sw * 16), src);
            }
        }
    }
    asm volatile("cp.async.commit_group;" ::: "memory");
}

__global__ __launch_bounds__(256, 1)
void gemm_f16_kernel(const __half* __restrict__ Ahi, const __half* __restrict__ Alo,
                     const __half* __restrict__ B,
                     const float* __restrict__ bias, float* __restrict__ C,
                     int M, int N, int K, int hasBias)
{
    extern __shared__ __align__(1024) char smem[];
    uint32_t sb = s2u(smem);
    int tid = threadIdx.x, lane = tid & 31, wid = tid >> 5;
    int wm = wid & 1, wn = wid >> 1;               // 2 x 4 warp grid, 64x64 warp tile
    size_t m0 = (size_t)blockIdx.y * GBM;
    size_t n0 = (size_t)blockIdx.x * GBN;
    const int NS = K / GBK;

    float acc[4][8][4];
#pragma unroll
    for (int mt = 0; mt < 4; mt++)
#pragma unroll
        for (int nt = 0; nt < 8; nt++)
#pragma unroll
            for (int j = 0; j < 4; j++) acc[mt][nt][j] = 0.f;

    gemm_load_stage(0, 0, NS, sb, Ahi, Alo, B, m0, n0, K, tid);
    gemm_load_stage(1, 1, NS, sb, Ahi, Alo, B, m0, n0, K, tid);
    gemm_load_stage(2, 2, NS, sb, Ahi, Alo, B, m0, n0, K, tid);

    int arow_b = wm * 64 + (lane & 15);            // + mt*16
    int achb   = lane >> 4;                        // + 2*ks
    int brow_b = wn * 64 + (lane & 7) + ((lane >> 4) & 1) * 8;   // + np*16
    int bchb   = (lane >> 3) & 1;                  // + 2*ks

    for (int s = 0; s < NS; s++) {
        asm volatile("cp.async.wait_group %0;" :: "n"(NSTAGE - 2));
        __syncthreads();
        gemm_load_stage((s + 3) & 3, s + 3, NS, sb, Ahi, Alo, B, m0, n0, K, tid);
        uint32_t st = sb + (uint32_t)(s & 3) * STG;
#pragma unroll
        for (int ks = 0; ks < 2; ks++) {
            uint32_t a[2][4][4];                    // [hi/lo][mt]
#pragma unroll
            for (int hl = 0; hl < 2; hl++)
#pragma unroll
                for (int mt = 0; mt < 4; mt++) {
                    int row = arow_b + mt * 16;
                    int ch = achb + 2 * ks;
                    int sw = ch ^ ((row >> 1) & 3);
                    LDSM4(a[hl][mt], st + (uint32_t)hl * 8192u + (uint32_t)(row * 64 + sw * 16));
                }
#pragma unroll
            for (int np = 0; np < 4; np++) {
                int row = brow_b + np * 16;
                int ch = bchb + 2 * ks;
                int sw = ch ^ ((row >> 1) & 3);
                uint32_t b[4];
                LDSM4(b, st + 16384u + (uint32_t)(row * 64 + sw * 16));
                // term-outer: same-accumulator reuse distance = 8 MMAs
#pragma unroll
                for (int term = 0; term < 2; term++) {
#pragma unroll
                    for (int mt = 0; mt < 4; mt++) {
#pragma unroll
                        for (int half = 0; half < 2; half++) {
                            MMA_F16(acc[mt][np * 2 + half], a[term][mt], &b[half * 2]);
                        }
                    }
                }
            }
        }
    }

    // epilogue
#pragma unroll
    for (int mt = 0; mt < 4; mt++) {
        size_t row = m0 + wm * 64 + mt * 16 + (lane >> 2);
#pragma unroll
        for (int half = 0; half < 2; half++) {
            float* Cp = C + (row + half * 8) * (size_t)N + n0 + wn * 64 + (lane & 3) * 2;
#pragma unroll
            for (int nt = 0; nt < 8; nt++) {
                float2 v;
                v.x = acc[mt][nt][half * 2];
                v.y = acc[mt][nt][half * 2 + 1];
                if (hasBias) {
                    int col = (int)(n0 + wn * 64 + nt * 8 + (lane & 3) * 2);
                    v.x += __ldg(&bias[col]);
                    v.y += __ldg(&bias[col + 1]);
                }
                *(float2*)(Cp + nt * 8) = v;
            }
        }
    }
}

// ---------------- fast exp (FMA pipe) ----------------
__device__ __forceinline__ float fast_exp(float x) {
    float t = x * 1.4426950408889634f;
    t = fminf(fmaxf(t, -126.f), 126.f);
    float z = t + 12582912.f;
    int i = __float_as_int(z);
    float f = t - (z - 12582912.f);
    float p = 1.5403530e-4f;
    p = fmaf(p, f, 1.3333558e-3f);
    p = fmaf(p, f, 9.6181291e-3f);
    p = fmaf(p, f, 5.5504109e-2f);
    p = fmaf(p, f, 2.4022651e-1f);
    p = fmaf(p, f, 6.9314718e-1f);
    p = fmaf(p, f, 1.0f);
    return __int_as_float(__float_as_int(p) + (i << 23));
}
__device__ __forceinline__ float rcp_approx(float x) {
    float r; asm("rcp.approx.f32 %0, %1;" : "=f"(r) : "f"(x)); return r;
}
__device__ __forceinline__ float sqrt_approx(float x) {
    float r; asm("sqrt.approx.f32 %0, %1;" : "=f"(r) : "f"(x)); return r;
}

// ---------------- gates + within-chunk clamped scan ----------------
__global__ __launch_bounds__(256) void gate_intra_kernel(
    const float* __restrict__ aiv, const float* __restrict__ bias,
    float* __restrict__ intra_out, float* __restrict__ cd_out,
    float* __restrict__ S_out, float* __restrict__ D_out)
{
    int g = blockIdx.x * 256 + threadIdx.x;
    int d = g & (DR - 1);
    int n = (g >> 10) & (NCHUNK - 1);
    int b = g >> 17;

    float bd = bias[d];
    float cd = 1.f, inv_cd = 1.f, wsum = 0.f, intra = 0.f;
    size_t row0 = (size_t)b * SEQ + (size_t)n * CHUNK;

    for (int t = 0; t < CHUNK; t++) {
        size_t row = row0 + t;
        const float* p = aiv + row * DR3;
        float ap  = p[d];
        float ipr = p[d + DR];
        float v   = p[d + 2 * DR];

        float ea = fast_exp(-(ap + bd));
        float ua = 1.f + ea;                 // = 1/a
        float ei = fast_exp(-ipr);
        float ui = 1.f + ei;                 // = 1/i
        float r = rcp_approx(ua * ui);
        float a  = r * ui;
        float ii = r * ua;
        float sig = sqrt_approx(fmaxf(fmaf(-a, a, 1.f), 1e-8f)) * (ii * v);

        cd *= a;
        inv_cd *= ua;
        float w = (cd >= 1e-10f) ? inv_cd : 1e10f;
        wsum = fmaf(sig, w, wsum);
        intra = cd * wsum;

        size_t o = row * DR + d;
        intra_out[o] = intra;
        cd_out[o]    = cd;
    }
    S_out[g] = intra;
    D_out[g] = cd;
}

// ---------------- chunk-level recurrence (reference-exact log/exp path) ----------------
__global__ void chunk_scan_kernel(const float* __restrict__ S, const float* __restrict__ D,
                                  float* __restrict__ inc)
{
    int g = blockIdx.x * blockDim.x + threadIdx.x;
    if (g >= BATCH * DR) return;
    int d = g & (DR - 1);
    int b = g >> 10;

    float cum_log = 0.f, cumW = 0.f;
    float prevP = 1.f, prevW = 0.f;
    size_t base = (size_t)b * NCHUNK * DR + d;

    for (int n = 0; n < NCHUNK; n++) {
        size_t idx = base + (size_t)n * DR;
        inc[idx] = prevP * prevW;
        cum_log += logf(fmaxf(D[idx], 1e-10f));
        float cumP = expf(cum_log);
        cumW += S[idx] / fmaxf(cumP, 1e-10f);
        prevP = cumP;
        prevW = cumW;
    }
}

// ---------------- cross-chunk fixup + fp16 hi/lo split of h ----------------
__global__ __launch_bounds__(256) void apply_cross_split_kernel(
    const float* __restrict__ intra, const float* __restrict__ cd,
    const float* __restrict__ inc,
    __half* __restrict__ hhi, __half* __restrict__ hlo)
{
    size_t i4 = (size_t)blockIdx.x * 256 + threadIdx.x;
    size_t base = i4 * 4;
    int d = (int)(base & (DR - 1));
    size_t row = base >> 10;
    int t = (int)(row & (SEQ - 1));
    int b = (int)(row >> 13);
    int n = t >> 6;

    float4 iv = ((const float4*)intra)[i4];
    float4 cv = ((const float4*)cd)[i4];
    float4 nv = *(const float4*)(inc + (((size_t)(b * NCHUNK + n)) << 10) + d);

    float h[4];
    h[0] = fmaf(cv.x, nv.x, iv.x);
    h[1] = fmaf(cv.y, nv.y, iv.y);
    h[2] = fmaf(cv.z, nv.z, iv.z);
    h[3] = fmaf(cv.w, nv.w, iv.w);

    ushort4 sh, sl;
    unsigned short* shp = &sh.x;
    unsigned short* slp = &sl.x;
#pragma unroll
    for (int j = 0; j < 4; j++) {
        __half hi = __float2half_rn(h[j]);
        __half lo = __float2half_rn(h[j] - __half2float(hi));
        shp[j] = __half_as_ushort(hi);
        slp[j] = __half_as_ushort(lo);
    }
    ((ushort4*)hhi)[i4] = sh;
    ((ushort4*)hlo)[i4] = sl;
}

// ---------------- split x into fp16 hi/lo ----------------
__global__ __launch_bounds__(256) void split_kernel(const float* __restrict__ x,
                                                    __half* __restrict__ hi,
                                                    __half* __restrict__ lo)
{
    size_t i = (size_t)blockIdx.x * 256 + threadIdx.x;
    float4 v = ((const float4*)x)[i];
    float vv[4] = { v.x, v.y, v.z, v.w };
    ushort4 sh, sl;
    unsigned short* shp = &sh.x;
    unsigned short* slp = &sl.x;
#pragma unroll
    for (int j = 0; j < 4; j++) {
        __half h = __float2half_rn(vv[j]);
        __half l = __float2half_rn(vv[j] - __half2float(h));
        shp[j] = __half_as_ushort(h);
        slp[j] = __half_as_ushort(l);
    }
    ((ushort4*)hi)[i] = sh;
    ((ushort4*)lo)[i] = sl;
}

// ---------------- transpose W[K][N] -> [N][K] fp16 ----------------
__global__ void transpose_half_kernel(const float* __restrict__ W,
                                      __half* __restrict__ T, int K, int N)
{
    __shared__ float tile[32][33];
    int n0 = blockIdx.x * 32, k0 = blockIdx.y * 32;
    int tx = threadIdx.x, ty = threadIdx.y;
#pragma unroll
    for (int i = 0; i < 32; i += 8)
        tile[ty + i][tx] = W[(size_t)(k0 + ty + i) * N + n0 + tx];
    __syncthreads();
#pragma unroll
    for (int i = 0; i < 32; i += 8)
        T[(size_t)(n0 + ty + i) * K + k0 + tx] = __float2half_rn(tile[tx][ty + i]);
}

// ---------------- launch ----------------
extern "C" void kernel_launch(void* const* d_in, const int* in_sizes, int n_in,
                              void* d_out, int out_size)
{
    const float* x          = (const float*)d_in[0];
    const float* W_aiv      = (const float*)d_in[1];
    const float* decay_bias = (const float*)d_in[2];
    const float* W_mix      = (const float*)d_in[3];
    const float* b_mix      = (const float*)d_in[4];
    float* out = (float*)d_out;

    char* pool = nullptr;
    cudaGetSymbolAddress((void**)&pool, g_pool);
    float* aiv    = (float*)(pool + OFF_AIV);
    __half* hhi   = (__half*)(pool + OFF_HHI);
    __half* hlo   = (__half*)(pool + OFF_HLO);
    __half* xhi   = (__half*)(pool + OFF_XHI);
    __half* xlo   = (__half*)(pool + OFF_XLO);
    float* intra  = (float*)(pool + OFF_INTRA);
    float* cd     = (float*)(pool + OFF_CD);
    float* Sp     = (float*)(pool + OFF_S);
    float* Dp     = (float*)(pool + OFF_D);
    float* incp   = (float*)(pool + OFF_INC);
    __half* wa    = (__half*)(pool + OFF_WA);
    __half* wm    = (__half*)(pool + OFF_WM);

    const int smem_bytes = NSTAGE * (int)STG;   // 131072
    cudaFuncSetAttribute(gemm_f16_kernel,
                         cudaFuncAttributeMaxDynamicSharedMemorySize, smem_bytes);

    // prep fp16 splits / conversions
    split_kernel<<<(MROWS * DM / 4) / 256, 256>>>(x, xhi, xlo);
    transpose_half_kernel<<<dim3(DR3 / 32, DM / 32), dim3(32, 8)>>>(W_aiv, wa, DM, DR3);
    transpose_half_kernel<<<dim3(DR / 32, DR / 32), dim3(32, 8)>>>(W_mix, wm, DR, DR);

    // 1. aiv = x @ W_aiv
    gemm_f16_kernel<<<dim3(DR3 / GBN, MROWS / GBM), 256, smem_bytes>>>(
        xhi, xlo, wa, nullptr, aiv, MROWS, DR3, DM, 0);

    // 2. gates + within-chunk scan
    gate_intra_kernel<<<(BATCH * NCHUNK * DR) / 256, 256>>>(aiv, decay_bias, intra, cd, Sp, Dp);

    // 3. chunk-level recurrence
    chunk_scan_kernel<<<(BATCH * DR) / 256, 256>>>(Sp, Dp, incp);

    // 4. cross-chunk fixup + fp16 split of h (reuses aiv region)
    apply_cross_split_kernel<<<(unsigned)((size_t)MROWS * DR / 4 / 256), 256>>>(
        intra, cd, incp, hhi, hlo);

    // 5. out = h @ W_mix + b_mix
    gemm_f16_kernel<<<dim3(DR / GBN, MROWS / GBM), 256, smem_bytes>>>(
        hhi, hlo, wm, b_mix, out, MROWS, DR, DR, 1);
}

// round 10
// speedup vs baseline: 1.9031x; 1.4429x over previous
#include <cuda_runtime.h>
#include <cuda_fp16.h>
#include <math.h>
#include <stdint.h>

// ---------------- problem constants ----------------
#define BATCH   4
#define SEQ     8192
#define DM      1024
#define DR      1024
#define DR3     3072
#define CHUNK   64
#define NCHUNK  128
#define MROWS   32768

// ---------------- scratch pool (bytes) ----------------
#define OFF_AIV   ((size_t)0)            // fp32 [MROWS][DR3]
#define OFF_HH    ((size_t)0)            // fp16 [MROWS][DR] (reuses aiv)
#define OFF_XH    ((size_t)402653184)    // fp16 [MROWS][DM]
#define OFF_INTRA ((size_t)536870912)
#define OFF_CD    ((size_t)671088640)
#define OFF_S     ((size_t)805306368)
#define OFF_D     ((size_t)807403520)
#define OFF_INC   ((size_t)809500672)
#define OFF_WA    ((size_t)811597824)    // fp16 [DR3][DM] transposed
#define OFF_WM    ((size_t)824180736)    // fp16 [DR][DR] transposed
#define POOL_BYTES ((size_t)828375040)

__device__ __align__(1024) char g_pool[POOL_BYTES];

// ---------------- helpers ----------------
__device__ __forceinline__ uint32_t s2u(const void* p) {
    uint32_t a;
    asm("{ .reg .u64 t; cvta.to.shared.u64 t, %1; cvt.u32.u64 %0, t; }" : "=r"(a) : "l"(p));
    return a;
}
__device__ __forceinline__ void cp16(uint32_t dst, const void* src) {
    asm volatile("cp.async.cg.shared.global [%0], [%1], 16;" :: "r"(dst), "l"(src));
}
#define LDSM4(r, addr) \
    asm volatile("ldmatrix.sync.aligned.m8n8.x4.shared.b16 {%0,%1,%2,%3}, [%4];" \
        : "=r"((r)[0]), "=r"((r)[1]), "=r"((r)[2]), "=r"((r)[3]) : "r"(addr))
#define MMA_F16(d, a, b) \
    asm volatile("mma.sync.aligned.m16n8k16.row.col.f32.f16.f16.f32 " \
        "{%0,%1,%2,%3}, {%4,%5,%6,%7}, {%8,%9}, {%0,%1,%2,%3};" \
        : "+f"((d)[0]), "+f"((d)[1]), "+f"((d)[2]), "+f"((d)[3]) \
        : "r"((a)[0]), "r"((a)[1]), "r"((a)[2]), "r"((a)[3]), "r"((b)[0]), "r"((b)[1]))

// ---------------- fp16 1-term GEMM, 128x256 CTA tile, 256 threads ----------------
// C[M,N] = A[M,K] @ B^T  (A,B fp16, B stored [N][K] K-contiguous, fp32 accumulate)
#define GBM 128
#define GBN 256
#define GBK 32
#define NSTAGE 4
#define STG 24576u   // A 8K | B 16K

__device__ __forceinline__ void gemm_load_stage(
    int buf, int kt, int NS, uint32_t sb,
    const __half* A, const __half* B,
    size_t m0, size_t n0, int K, int tid)
{
    if (kt < NS) {
        uint32_t base = sb + (uint32_t)buf * STG;
        size_t kbase = (size_t)kt * GBK;
#pragma unroll
        for (int i = 0; i < 6; i++) {
            int c = tid + i * 256;                  // 0..1535, region uniform per i
            if (c < 512) {                          // A: 128 rows x 4 chunks
                int row = c >> 2;
                int ch  = c & 3;
                int sw  = ch ^ ((row >> 1) & 3);
                const __half* src = A + (m0 + row) * (size_t)K + kbase + ch * 8;
                cp16(base + (uint32_t)(row * 64 + sw * 16), src);
            } else {                                // B: 256 rows x 4 chunks
                int cb  = c - 512;
                int row = cb >> 2;
                int ch  = cb & 3;
                int sw  = ch ^ ((row >> 1) & 3);
                const __half* src = B + (n0 + row) * (size_t)K + kbase + ch * 8;
                cp16(base + 8192u + (uint32_t)(row * 64 + sw * 16), src);
            }
        }
    }
    asm volatile("cp.async.commit_group;" ::: "memory");
}

__global__ __launch_bounds__(256, 1)
void gemm_f16_kernel(const __half* __restrict__ A, const __half* __restrict__ B,
                     const float* __restrict__ bias, float* __restrict__ C,
                     int M, int N, int K, int hasBias)
{
    extern __shared__ __align__(1024) char smem[];
    uint32_t sb = s2u(smem);
    int tid = threadIdx.x, lane = tid & 31, wid = tid >> 5;
    int wm = wid & 1, wn = wid >> 1;               // 2 x 4 warp grid, 64x64 warp tile
    size_t m0 = (size_t)blockIdx.y * GBM;
    size_t n0 = (size_t)blockIdx.x * GBN;
    const int NS = K / GBK;

    float acc[4][8][4];
#pragma unroll
    for (int mt = 0; mt < 4; mt++)
#pragma unroll
        for (int nt = 0; nt < 8; nt++)
#pragma unroll
            for (int j = 0; j < 4; j++) acc[mt][nt][j] = 0.f;

    gemm_load_stage(0, 0, NS, sb, A, B, m0, n0, K, tid);
    gemm_load_stage(1, 1, NS, sb, A, B, m0, n0, K, tid);
    gemm_load_stage(2, 2, NS, sb, A, B, m0, n0, K, tid);

    int arow_b = wm * 64 + (lane & 15);            // + mt*16
    int achb   = lane >> 4;                        // + 2*ks
    int brow_b = wn * 64 + (lane & 7) + ((lane >> 4) & 1) * 8;   // + np*16
    int bchb   = (lane >> 3) & 1;                  // + 2*ks

    for (int s = 0; s < NS; s++) {
        asm volatile("cp.async.wait_group %0;" :: "n"(NSTAGE - 2));
        __syncthreads();
        gemm_load_stage((s + 3) & 3, s + 3, NS, sb, A, B, m0, n0, K, tid);
        uint32_t st = sb + (uint32_t)(s & 3) * STG;
#pragma unroll
        for (int ks = 0; ks < 2; ks++) {
            uint32_t a[4][4];                       // [mt]
#pragma unroll
            for (int mt = 0; mt < 4; mt++) {
                int row = arow_b + mt * 16;
                int ch = achb + 2 * ks;
                int sw = ch ^ ((row >> 1) & 3);
                LDSM4(a[mt], st + (uint32_t)(row * 64 + sw * 16));
            }
#pragma unroll
            for (int np = 0; np < 4; np++) {
                int row = brow_b + np * 16;
                int ch = bchb + 2 * ks;
                int sw = ch ^ ((row >> 1) & 3);
                uint32_t b[4];
                LDSM4(b, st + 8192u + (uint32_t)(row * 64 + sw * 16));
#pragma unroll
                for (int mt = 0; mt < 4; mt++) {
#pragma unroll
                    for (int half = 0; half < 2; half++) {
                        MMA_F16(acc[mt][np * 2 + half], a[mt], &b[half * 2]);
                    }
                }
            }
        }
    }

    // epilogue
#pragma unroll
    for (int mt = 0; mt < 4; mt++) {
        size_t row = m0 + wm * 64 + mt * 16 + (lane >> 2);
#pragma unroll
        for (int half = 0; half < 2; half++) {
            float* Cp = C + (row + half * 8) * (size_t)N + n0 + wn * 64 + (lane & 3) * 2;
#pragma unroll
            for (int nt = 0; nt < 8; nt++) {
                float2 v;
                v.x = acc[mt][nt][half * 2];
                v.y = acc[mt][nt][half * 2 + 1];
                if (hasBias) {
                    int col = (int)(n0 + wn * 64 + nt * 8 + (lane & 3) * 2);
                    v.x += __ldg(&bias[col]);
                    v.y += __ldg(&bias[col + 1]);
                }
                *(float2*)(Cp + nt * 8) = v;
            }
        }
    }
}

// ---------------- fast exp (FMA pipe) ----------------
__device__ __forceinline__ float fast_exp(float x) {
    float t = x * 1.4426950408889634f;
    t = fminf(fmaxf(t, -126.f), 126.f);
    float z = t + 12582912.f;
    int i = __float_as_int(z);
    float f = t - (z - 12582912.f);
    float p = 1.5403530e-4f;
    p = fmaf(p, f, 1.3333558e-3f);
    p = fmaf(p, f, 9.6181291e-3f);
    p = fmaf(p, f, 5.5504109e-2f);
    p = fmaf(p, f, 2.4022651e-1f);
    p = fmaf(p, f, 6.9314718e-1f);
    p = fmaf(p, f, 1.0f);
    return __int_as_float(__float_as_int(p) + (i << 23));
}
__device__ __forceinline__ float rcp_approx(float x) {
    float r; asm("rcp.approx.f32 %0, %1;" : "=f"(r) : "f"(x)); return r;
}
__device__ __forceinline__ float sqrt_approx(float x) {
    float r; asm("sqrt.approx.f32 %0, %1;" : "=f"(r) : "f"(x)); return r;
}

// ---------------- gates + within-chunk clamped scan ----------------
__global__ __launch_bounds__(256) void gate_intra_kernel(
    const float* __restrict__ aiv, const float* __restrict__ bias,
    float* __restrict__ intra_out, float* __restrict__ cd_out,
    float* __restrict__ S_out, float* __restrict__ D_out)
{
    int g = blockIdx.x * 256 + threadIdx.x;
    int d = g & (DR - 1);
    int n = (g >> 10) & (NCHUNK - 1);
    int b = g >> 17;

    float bd = bias[d];
    float cd = 1.f, inv_cd = 1.f, wsum = 0.f, intra = 0.f;
    size_t row0 = (size_t)b * SEQ + (size_t)n * CHUNK;

    for (int t = 0; t < CHUNK; t++) {
        size_t row = row0 + t;
        const float* p = aiv + row * DR3;
        float ap  = p[d];
        float ipr = p[d + DR];
        float v   = p[d + 2 * DR];

        float ea = fast_exp(-(ap + bd));
        float ua = 1.f + ea;                 // = 1/a
        float ei = fast_exp(-ipr);
        float ui = 1.f + ei;                 // = 1/i
        float r = rcp_approx(ua * ui);
        float a  = r * ui;
        float ii = r * ua;
        float sig = sqrt_approx(fmaxf(fmaf(-a, a, 1.f), 1e-8f)) * (ii * v);

        cd *= a;
        inv_cd *= ua;
        float w = (cd >= 1e-10f) ? inv_cd : 1e10f;
        wsum = fmaf(sig, w, wsum);
        intra = cd * wsum;

        size_t o = row * DR + d;
        intra_out[o] = intra;
        cd_out[o]    = cd;
    }
    S_out[g] = intra;
    D_out[g] = cd;
}

// ---------------- chunk-level recurrence (reference-exact log/exp path) ----------------
__global__ void chunk_scan_kernel(const float* __restrict__ S, const float* __restrict__ D,
                                  float* __restrict__ inc)
{
    int g = blockIdx.x * blockDim.x + threadIdx.x;
    if (g >= BATCH * DR) return;
    int d = g & (DR - 1);
    int b = g >> 10;

    float cum_log = 0.f, cumW = 0.f;
    float prevP = 1.f, prevW = 0.f;
    size_t base = (size_t)b * NCHUNK * DR + d;

    for (int n = 0; n < NCHUNK; n++) {
        size_t idx = base + (size_t)n * DR;
        inc[idx] = prevP * prevW;
        cum_log += logf(fmaxf(D[idx], 1e-10f));
        float cumP = expf(cum_log);
        cumW += S[idx] / fmaxf(cumP, 1e-10f);
        prevP = cumP;
        prevW = cumW;
    }
}

// ---------------- cross-chunk fixup + fp16 convert of h ----------------
__global__ __launch_bounds__(256) void apply_cross_kernel(
    const float* __restrict__ intra, const float* __restrict__ cd,
    const float* __restrict__ inc,
    __half* __restrict__ hh)
{
    size_t i4 = (size_t)blockIdx.x * 256 + threadIdx.x;
    size_t base = i4 * 4;
    int d = (int)(base & (DR - 1));
    size_t row = base >> 10;
    int t = (int)(row & (SEQ - 1));
    int b = (int)(row >> 13);
    int n = t >> 6;

    float4 iv = ((const float4*)intra)[i4];
    float4 cv = ((const float4*)cd)[i4];
    float4 nv = *(const float4*)(inc + (((size_t)(b * NCHUNK + n)) << 10) + d);

    float h[4];
    h[0] = fmaf(cv.x, nv.x, iv.x);
    h[1] = fmaf(cv.y, nv.y, iv.y);
    h[2] = fmaf(cv.z, nv.z, iv.z);
    h[3] = fmaf(cv.w, nv.w, iv.w);

    ushort4 sh;
    unsigned short* shp = &sh.x;
#pragma unroll
    for (int j = 0; j < 4; j++)
        shp[j] = __half_as_ushort(__float2half_rn(h[j]));
    ((ushort4*)hh)[i4] = sh;
}

// ---------------- convert x to fp16 ----------------
__global__ __launch_bounds__(256) void convert_kernel(const float* __restrict__ x,
                                                      __half* __restrict__ xh)
{
    size_t i = (size_t)blockIdx.x * 256 + threadIdx.x;
    float4 v = ((const float4*)x)[i];
    ushort4 sh;
    sh.x = __half_as_ushort(__float2half_rn(v.x));
    sh.y = __half_as_ushort(__float2half_rn(v.y));
    sh.z = __half_as_ushort(__float2half_rn(v.z));
    sh.w = __half_as_ushort(__float2half_rn(v.w));
    ((ushort4*)xh)[i] = sh;
}

// ---------------- transpose W[K][N] -> [N][K] fp16 ----------------
__global__ void transpose_half_kernel(const float* __restrict__ W,
                                      __half* __restrict__ T, int K, int N)
{
    __shared__ float tile[32][33];
    int n0 = blockIdx.x * 32, k0 = blockIdx.y * 32;
    int tx = threadIdx.x, ty = threadIdx.y;
#pragma unroll
    for (int i = 0; i < 32; i += 8)
        tile[ty + i][tx] = W[(size_t)(k0 + ty + i) * N + n0 + tx];
    __syncthreads();
#pragma unroll
    for (int i = 0; i < 32; i += 8)
        T[(size_t)(n0 + ty + i) * K + k0 + tx] = __float2half_rn(tile[tx][ty + i]);
}

// ---------------- launch ----------------
extern "C" void kernel_launch(void* const* d_in, const int* in_sizes, int n_in,
                              void* d_out, int out_size)
{
    const float* x          = (const float*)d_in[0];
    const float* W_aiv      = (const float*)d_in[1];
    const float* decay_bias = (const float*)d_in[2];
    const float* W_mix      = (const float*)d_in[3];
    const float* b_mix      = (const float*)d_in[4];
    float* out = (float*)d_out;

    char* pool = nullptr;
    cudaGetSymbolAddress((void**)&pool, g_pool);
    float* aiv    = (float*)(pool + OFF_AIV);
    __half* hh    = (__half*)(pool + OFF_HH);
    __half* xh    = (__half*)(pool + OFF_XH);
    float* intra  = (float*)(pool + OFF_INTRA);
    float* cd     = (float*)(pool + OFF_CD);
    float* Sp     = (float*)(pool + OFF_S);
    float* Dp     = (float*)(pool + OFF_D);
    float* incp   = (float*)(pool + OFF_INC);
    __half* wa    = (__half*)(pool + OFF_WA);
    __half* wm    = (__half*)(pool + OFF_WM);

    const int smem_bytes = NSTAGE * (int)STG;   // 98304
    cudaFuncSetAttribute(gemm_f16_kernel,
                         cudaFuncAttributeMaxDynamicSharedMemorySize, smem_bytes);

    // prep fp16 conversions
    convert_kernel<<<(MROWS * DM / 4) / 256, 256>>>(x, xh);
    transpose_half_kernel<<<dim3(DR3 / 32, DM / 32), dim3(32, 8)>>>(W_aiv, wa, DM, DR3);
    transpose_half_kernel<<<dim3(DR / 32, DR / 32), dim3(32, 8)>>>(W_mix, wm, DR, DR);

    // 1. aiv = x @ W_aiv
    gemm_f16_kernel<<<dim3(DR3 / GBN, MROWS / GBM), 256, smem_bytes>>>(
        xh, wa, nullptr, aiv, MROWS, DR3, DM, 0);

    // 2. gates + within-chunk scan
    gate_intra_kernel<<<(BATCH * NCHUNK * DR) / 256, 256>>>(aiv, decay_bias, intra, cd, Sp, Dp);

    // 3. chunk-level recurrence
    chunk_scan_kernel<<<(BATCH * DR) / 256, 256>>>(Sp, Dp, incp);

    // 4. cross-chunk fixup + fp16 convert of h (reuses aiv region)
    apply_cross_kernel<<<(unsigned)((size_t)MROWS * DR / 4 / 256), 256>>>(
        intra, cd, incp, hh);

    // 5. out = h @ W_mix + b_mix
    gemm_f16_kernel<<<dim3(DR / GBN, MROWS / GBM), 256, smem_bytes>>>(
        hh, wm, b_mix, out, MROWS, DR, DR, 1);
}

// round 13
// speedup vs baseline: 2.1979x; 1.1549x over previous
#include <cuda_runtime.h>
#include <cuda_fp16.h>
#include <math.h>
#include <stdint.h>

// ---------------- problem constants ----------------
#define BATCH   4
#define SEQ     8192
#define DM      1024
#define DR      1024
#define DR3     3072
#define CHUNK   64
#define NCHUNK  128
#define MROWS   32768

// ---------------- scratch pool (bytes) ----------------
#define OFF_AIV   ((size_t)0)            // fp32 [MROWS][DR3]
#define OFF_HH    ((size_t)0)            // fp16 [MROWS][DR] (reuses aiv)
#define OFF_XH    ((size_t)402653184)    // fp16 [MROWS][DM]
#define OFF_INTRA ((size_t)536870912)
#define OFF_CD    ((size_t)671088640)
#define OFF_S     ((size_t)805306368)
#define OFF_D     ((size_t)807403520)
#define OFF_INC   ((size_t)809500672)
#define OFF_WA    ((size_t)811597824)    // fp16 [DR3][DM] transposed
#define OFF_WM    ((size_t)824180736)    // fp16 [DR][DR] transposed
#define POOL_BYTES ((size_t)828375040)

__device__ __align__(1024) char g_pool[POOL_BYTES];

// ---------------- helpers ----------------
__device__ __forceinline__ uint32_t s2u(const void* p) {
    uint32_t a;
    asm("{ .reg .u64 t; cvta.to.shared.u64 t, %1; cvt.u32.u64 %0, t; }" : "=r"(a) : "l"(p));
    return a;
}
__device__ __forceinline__ void cp16(uint32_t dst, const void* src) {
    asm volatile("cp.async.cg.shared.global [%0], [%1], 16;" :: "r"(dst), "l"(src));
}
#define LDSM4(r, addr) \
    asm volatile("ldmatrix.sync.aligned.m8n8.x4.shared.b16 {%0,%1,%2,%3}, [%4];" \
        : "=r"((r)[0]), "=r"((r)[1]), "=r"((r)[2]), "=r"((r)[3]) : "r"(addr))
#define MMA_F16(d, a, b) \
    asm volatile("mma.sync.aligned.m16n8k16.row.col.f32.f16.f16.f32 " \
        "{%0,%1,%2,%3}, {%4,%5,%6,%7}, {%8,%9}, {%0,%1,%2,%3};" \
        : "+f"((d)[0]), "+f"((d)[1]), "+f"((d)[2]), "+f"((d)[3]) \
        : "r"((a)[0]), "r"((a)[1]), "r"((a)[2]), "r"((a)[3]), "r"((b)[0]), "r"((b)[1]))

// ---------------- fp16 1-term GEMM, 128x128 CTA tile, 256 threads, 2 CTAs/SM ----
// C[M,N] = A[M,K] @ B^T  (A,B fp16, B stored [N][K] K-contiguous, fp32 accumulate)
#define GBM 128
#define GBN 128
#define GBK 32
#define NSTAGE 4
#define STG 16384u   // A 8K | B 8K

__device__ __forceinline__ void gemm_load_stage(
    int buf, int kt, int NS, uint32_t sb,
    const __half* A, const __half* B,
    size_t m0, size_t n0, int K, int tid)
{
    if (kt < NS) {
        uint32_t base = sb + (uint32_t)buf * STG;
        size_t kbase = (size_t)kt * GBK;
#pragma unroll
        for (int i = 0; i < 4; i++) {
            int c = tid + i * 256;                  // 0..1023, region uniform per i
            if (c < 512) {                          // A: 128 rows x 4 chunks
                int row = c >> 2;
                int ch  = c & 3;
                int sw  = ch ^ ((row >> 1) & 3);
                const __half* src = A + (m0 + row) * (size_t)K + kbase + ch * 8;
                cp16(base + (uint32_t)(row * 64 + sw * 16), src);
            } else {                                // B: 128 rows x 4 chunks
                int cb  = c - 512;
                int row = cb >> 2;
                int ch  = cb & 3;
                int sw  = ch ^ ((row >> 1) & 3);
                const __half* src = B + (n0 + row) * (size_t)K + kbase + ch * 8;
                cp16(base + 8192u + (uint32_t)(row * 64 + sw * 16), src);
            }
        }
    }
    asm volatile("cp.async.commit_group;" ::: "memory");
}

__global__ __launch_bounds__(256, 2)
void gemm_f16_kernel(const __half* __restrict__ A, const __half* __restrict__ B,
                     const float* __restrict__ bias, float* __restrict__ C,
                     int M, int N, int K, int hasBias)
{
    extern __shared__ __align__(1024) char smem[];
    uint32_t sb = s2u(smem);
    int tid = threadIdx.x, lane = tid & 31, wid = tid >> 5;
    int wm = wid & 3, wn = wid >> 2;               // 4 x 2 warp grid, 32x64 warp tile
    size_t m0 = (size_t)blockIdx.y * GBM;
    size_t n0 = (size_t)blockIdx.x * GBN;
    const int NS = K / GBK;

    float acc[2][8][4];
#pragma unroll
    for (int mt = 0; mt < 2; mt++)
#pragma unroll
        for (int nt = 0; nt < 8; nt++)
#pragma unroll
            for (int j = 0; j < 4; j++) acc[mt][nt][j] = 0.f;

    gemm_load_stage(0, 0, NS, sb, A, B, m0, n0, K, tid);
    gemm_load_stage(1, 1, NS, sb, A, B, m0, n0, K, tid);
    gemm_load_stage(2, 2, NS, sb, A, B, m0, n0, K, tid);

    int arow_b = wm * 32 + (lane & 15);            // + mt*16
    int achb   = lane >> 4;                        // + 2*ks
    int brow_b = wn * 64 + (lane & 7) + ((lane >> 4) & 1) * 8;   // + np*16
    int bchb   = (lane >> 3) & 1;                  // + 2*ks

    for (int s = 0; s < NS; s++) {
        asm volatile("cp.async.wait_group %0;" :: "n"(NSTAGE - 2));
        __syncthreads();
        gemm_load_stage((s + 3) & 3, s + 3, NS, sb, A, B, m0, n0, K, tid);
        uint32_t st = sb + (uint32_t)(s & 3) * STG;
#pragma unroll
        for (int ks = 0; ks < 2; ks++) {
            uint32_t a[2][4];                       // [mt]
#pragma unroll
            for (int mt = 0; mt < 2; mt++) {
                int row = arow_b + mt * 16;
                int ch = achb + 2 * ks;
                int sw = ch ^ ((row >> 1) & 3);
                LDSM4(a[mt], st + (uint32_t)(row * 64 + sw * 16));
            }
#pragma unroll
            for (int np = 0; np < 4; np++) {
                int row = brow_b + np * 16;
                int ch = bchb + 2 * ks;
                int sw = ch ^ ((row >> 1) & 3);
                uint32_t b[4];
                LDSM4(b, st + 8192u + (uint32_t)(row * 64 + sw * 16));
#pragma unroll
                for (int mt = 0; mt < 2; mt++) {
#pragma unroll
                    for (int half = 0; half < 2; half++) {
                        MMA_F16(acc[mt][np * 2 + half], a[mt], &b[half * 2]);
                    }
                }
            }
        }
    }

    // epilogue
#pragma unroll
    for (int mt = 0; mt < 2; mt++) {
        size_t row = m0 + wm * 32 + mt * 16 + (lane >> 2);
#pragma unroll
        for (int half = 0; half < 2; half++) {
            float* Cp = C + (row + half * 8) * (size_t)N + n0 + wn * 64 + (lane & 3) * 2;
#pragma unroll
            for (int nt = 0; nt < 8; nt++) {
                float2 v;
                v.x = acc[mt][nt][half * 2];
                v.y = acc[mt][nt][half * 2 + 1];
                if (hasBias) {
                    int col = (int)(n0 + wn * 64 + nt * 8 + (lane & 3) * 2);
                    v.x += __ldg(&bias[col]);
                    v.y += __ldg(&bias[col + 1]);
                }
                *(float2*)(Cp + nt * 8) = v;
            }
        }
    }
}

// ---------------- fast exp (FMA pipe) ----------------
__device__ __forceinline__ float fast_exp(float x) {
    float t = x * 1.4426950408889634f;
    t = fminf(fmaxf(t, -126.f), 126.f);
    float z = t + 12582912.f;
    int i = __float_as_int(z);
    float f = t - (z - 12582912.f);
    float p = 1.5403530e-4f;
    p = fmaf(p, f, 1.3333558e-3f);
    p = fmaf(p, f, 9.6181291e-3f);
    p = fmaf(p, f, 5.5504109e-2f);
    p = fmaf(p, f, 2.4022651e-1f);
    p = fmaf(p, f, 6.9314718e-1f);
    p = fmaf(p, f, 1.0f);
    return __int_as_float(__float_as_int(p) + (i << 23));
}
__device__ __forceinline__ float rcp_approx(float x) {
    float r; asm("rcp.approx.f32 %0, %1;" : "=f"(r) : "f"(x)); return r;
}
__device__ __forceinline__ float sqrt_approx(float x) {
    float r; asm("sqrt.approx.f32 %0, %1;" : "=f"(r) : "f"(x)); return r;
}

// ---------------- gates + within-chunk clamped scan ----------------
__global__ __launch_bounds__(256) void gate_intra_kernel(
    const float* __restrict__ aiv, const float* __restrict__ bias,
    float* __restrict__ intra_out, float* __restrict__ cd_out,
    float* __restrict__ S_out, float* __restrict__ D_out)
{
    int g = blockIdx.x * 256 + threadIdx.x;
    int d = g & (DR - 1);
    int n = (g >> 10) & (NCHUNK - 1);
    int b = g >> 17;

    float bd = bias[d];
    float cd = 1.f, inv_cd = 1.f, wsum = 0.f, intra = 0.f;
    size_t row0 = (size_t)b * SEQ + (size_t)n * CHUNK;

    for (int t = 0; t < CHUNK; t++) {
        size_t row = row0 + t;
        const float* p = aiv + row * DR3;
        float ap  = p[d];
        float ipr = p[d + DR];
        float v   = p[d + 2 * DR];

        float ea = fast_exp(-(ap + bd));
        float ua = 1.f + ea;                 // = 1/a
        float ei = fast_exp(-ipr);
        float ui = 1.f + ei;                 // = 1/i
        float r = rcp_approx(ua * ui);
        float a  = r * ui;
        float ii = r * ua;
        float sig = sqrt_approx(fmaxf(fmaf(-a, a, 1.f), 1e-8f)) * (ii * v);

        cd *= a;
        inv_cd *= ua;
        float w = (cd >= 1e-10f) ? inv_cd : 1e10f;
        wsum = fmaf(sig, w, wsum);
        intra = cd * wsum;

        size_t o = row * DR + d;
        intra_out[o] = intra;
        cd_out[o]    = cd;
    }
    S_out[g] = intra;
    D_out[g] = cd;
}

// ---------------- chunk-level recurrence (reference-exact log/exp path) ----------------
__global__ void chunk_scan_kernel(const float* __restrict__ S, const float* __restrict__ D,
                                  float* __restrict__ inc)
{
    int g = blockIdx.x * blockDim.x + threadIdx.x;
    if (g >= BATCH * DR) return;
    int d = g & (DR - 1);
    int b = g >> 10;

    float cum_log = 0.f, cumW = 0.f;
    float prevP = 1.f, prevW = 0.f;
    size_t base = (size_t)b * NCHUNK * DR + d;

    for (int n = 0; n < NCHUNK; n++) {
        size_t idx = base + (size_t)n * DR;
        inc[idx] = prevP * prevW;
        cum_log += logf(fmaxf(D[idx], 1e-10f));
        float cumP = expf(cum_log);
        cumW += S[idx] / fmaxf(cumP, 1e-10f);
        prevP = cumP;
        prevW = cumW;
    }
}

// ---------------- cross-chunk fixup + fp16 convert of h ----------------
__global__ __launch_bounds__(256) void apply_cross_kernel(
    const float* __restrict__ intra, const float* __restrict__ cd,
    const float* __restrict__ inc,
    __half* __restrict__ hh)
{
    size_t i4 = (size_t)blockIdx.x * 256 + threadIdx.x;
    size_t base = i4 * 4;
    int d = (int)(base & (DR - 1));
    size_t row = base >> 10;
    int t = (int)(row & (SEQ - 1));
    int b = (int)(row >> 13);
    int n = t >> 6;

    float4 iv = ((const float4*)intra)[i4];
    float4 cv = ((const float4*)cd)[i4];
    float4 nv = *(const float4*)(inc + (((size_t)(b * NCHUNK + n)) << 10) + d);

    float h[4];
    h[0] = fmaf(cv.x, nv.x, iv.x);
    h[1] = fmaf(cv.y, nv.y, iv.y);
    h[2] = fmaf(cv.z, nv.z, iv.z);
    h[3] = fmaf(cv.w, nv.w, iv.w);

    ushort4 sh;
    unsigned short* shp = &sh.x;
#pragma unroll
    for (int j = 0; j < 4; j++)
        shp[j] = __half_as_ushort(__float2half_rn(h[j]));
    ((ushort4*)hh)[i4] = sh;
}

// ---------------- convert x to fp16 ----------------
__global__ __launch_bounds__(256) void convert_kernel(const float* __restrict__ x,
                                                      __half* __restrict__ xh)
{
    size_t i = (size_t)blockIdx.x * 256 + threadIdx.x;
    float4 v = ((const float4*)x)[i];
    ushort4 sh;
    sh.x = __half_as_ushort(__float2half_rn(v.x));
    sh.y = __half_as_ushort(__float2half_rn(v.y));
    sh.z = __half_as_ushort(__float2half_rn(v.z));
    sh.w = __half_as_ushort(__float2half_rn(v.w));
    ((ushort4*)xh)[i] = sh;
}

// ---------------- transpose W[K][N] -> [N][K] fp16 ----------------
__global__ void transpose_half_kernel(const float* __restrict__ W,
                                      __half* __restrict__ T, int K, int N)
{
    __shared__ float tile[32][33];
    int n0 = blockIdx.x * 32, k0 = blockIdx.y * 32;
    int tx = threadIdx.x, ty = threadIdx.y;
#pragma unroll
    for (int i = 0; i < 32; i += 8)
        tile[ty + i][tx] = W[(size_t)(k0 + ty + i) * N + n0 + tx];
    __syncthreads();
#pragma unroll
    for (int i = 0; i < 32; i += 8)
        T[(size_t)(n0 + ty + i) * K + k0 + tx] = __float2half_rn(tile[tx][ty + i]);
}

// ---------------- launch ----------------
extern "C" void kernel_launch(void* const* d_in, const int* in_sizes, int n_in,
                              void* d_out, int out_size)
{
    const float* x          = (const float*)d_in[0];
    const float* W_aiv      = (const float*)d_in[1];
    const float* decay_bias = (const float*)d_in[2];
    const float* W_mix      = (const float*)d_in[3];
    const float* b_mix      = (const float*)d_in[4];
    float* out = (float*)d_out;

    char* pool = nullptr;
    cudaGetSymbolAddress((void**)&pool, g_pool);
    float* aiv    = (float*)(pool + OFF_AIV);
    __half* hh    = (__half*)(pool + OFF_HH);
    __half* xh    = (__half*)(pool + OFF_XH);
    float* intra  = (float*)(pool + OFF_INTRA);
    float* cd     = (float*)(pool + OFF_CD);
    float* Sp     = (float*)(pool + OFF_S);
    float* Dp     = (float*)(pool + OFF_D);
    float* incp   = (float*)(pool + OFF_INC);
    __half* wa    = (__half*)(pool + OFF_WA);
    __half* wm    = (__half*)(pool + OFF_WM);

    const int smem_bytes = NSTAGE * (int)STG;   // 65536
    cudaFuncSetAttribute(gemm_f16_kernel,
                         cudaFuncAttributeMaxDynamicSharedMemorySize, smem_bytes);

    // prep fp16 conversions
    convert_kernel<<<(MROWS * DM / 4) / 256, 256>>>(x, xh);
    transpose_half_kernel<<<dim3(DR3 / 32, DM / 32), dim3(32, 8)>>>(W_aiv, wa, DM, DR3);
    transpose_half_kernel<<<dim3(DR / 32, DR / 32), dim3(32, 8)>>>(W_mix, wm, DR, DR);

    // 1. aiv = x @ W_aiv
    gemm_f16_kernel<<<dim3(DR3 / GBN, MROWS / GBM), 256, smem_bytes>>>(
        xh, wa, nullptr, aiv, MROWS, DR3, DM, 0);

    // 2. gates + within-chunk scan
    gate_intra_kernel<<<(BATCH * NCHUNK * DR) / 256, 256>>>(aiv, decay_bias, intra, cd, Sp, Dp);

    // 3. chunk-level recurrence
    chunk_scan_kernel<<<(BATCH * DR) / 256, 256>>>(Sp, Dp, incp);

    // 4. cross-chunk fixup + fp16 convert of h (reuses aiv region)
    apply_cross_kernel<<<(unsigned)((size_t)MROWS * DR / 4 / 256), 256>>>(
        intra, cd, incp, hh);

    // 5. out = h @ W_mix + b_mix
    gemm_f16_kernel<<<dim3(DR / GBN, MROWS / GBM), 256, smem_bytes>>>(
        hh, wm, b_mix, out, MROWS, DR, DR, 1);
}

// round 15
// speedup vs baseline: 2.4163x; 1.0994x over previous
#include <cuda_runtime.h>
#include <cuda_fp16.h>
#include <math.h>
#include <stdint.h>

// ---------------- problem constants ----------------
#define BATCH   4
#define SEQ     8192
#define DM      1024
#define DR      1024
#define DR3     3072
#define CHUNK   64
#define NCHUNK  128
#define MROWS   32768

// ---------------- scratch pool (bytes) ----------------
#define OFF_AIV   ((size_t)0)            // fp32 [MROWS][DR3]
#define OFF_HH    ((size_t)0)            // fp16 [MROWS][DR] (reuses aiv)
#define OFF_XH    ((size_t)402653184)    // fp16 [MROWS][DM]
#define OFF_INTRA ((size_t)536870912)
#define OFF_CD    ((size_t)671088640)
#define OFF_S     ((size_t)805306368)
#define OFF_D     ((size_t)807403520)
#define OFF_INC   ((size_t)809500672)
#define OFF_WA    ((size_t)811597824)    // fp16 [DR3][DM] transposed
#define OFF_WM    ((size_t)824180736)    // fp16 [DR][DR] transposed
#define POOL_BYTES ((size_t)828375040)

__device__ __align__(1024) char g_pool[POOL_BYTES];

// ---------------- helpers ----------------
__device__ __forceinline__ uint32_t s2u(const void* p) {
    uint32_t a;
    asm("{ .reg .u64 t; cvta.to.shared.u64 t, %1; cvt.u32.u64 %0, t; }" : "=r"(a) : "l"(p));
    return a;
}
__device__ __forceinline__ void cp16(uint32_t dst, const void* src) {
    asm volatile("cp.async.cg.shared.global [%0], [%1], 16;" :: "r"(dst), "l"(src));
}
#define LDSM4(r, addr) \
    asm volatile("ldmatrix.sync.aligned.m8n8.x4.shared.b16 {%0,%1,%2,%3}, [%4];" \
        : "=r"((r)[0]), "=r"((r)[1]), "=r"((r)[2]), "=r"((r)[3]) : "r"(addr))
#define MMA_F16(d, a, b) \
    asm volatile("mma.sync.aligned.m16n8k16.row.col.f32.f16.f16.f32 " \
        "{%0,%1,%2,%3}, {%4,%5,%6,%7}, {%8,%9}, {%0,%1,%2,%3};" \
        : "+f"((d)[0]), "+f"((d)[1]), "+f"((d)[2]), "+f"((d)[3]) \
        : "r"((a)[0]), "r"((a)[1]), "r"((a)[2]), "r"((a)[3]), "r"((b)[0]), "r"((b)[1]))

// ---------------- fp16 1-term GEMM, 128x128 tile, GBK=64, 3 stages, 2 CTAs/SM --
// C[M,N] = A[M,K] @ B^T  (A,B fp16, B stored [N][K] K-contiguous, fp32 accumulate)
// smem rows are 128 B (64 halves); swizzle: chunk ^= (row & 7)
#define GBM 128
#define GBN 128
#define GBK 64
#define NSTAGE 3
#define STG 32768u   // A 16K | B 16K

__device__ __forceinline__ void gemm_load_stage(
    int buf, int kt, int NS, uint32_t sb,
    const __half* A, const __half* B,
    size_t m0, size_t n0, int K, int tid)
{
    if (kt < NS) {
        uint32_t base = sb + (uint32_t)buf * STG;
        size_t kbase = (size_t)kt * GBK;
#pragma unroll
        for (int i = 0; i < 8; i++) {
            int c = tid + i * 256;                  // 0..2047, region uniform per i
            if (c < 1024) {                         // A: 128 rows x 8 chunks
                int row = c >> 3;
                int ch  = c & 7;
                int sw  = ch ^ (row & 7);
                const __half* src = A + (m0 + row) * (size_t)K + kbase + ch * 8;
                cp16(base + (uint32_t)(row * 128 + sw * 16), src);
            } else {                                // B: 128 rows x 8 chunks
                int cb  = c - 1024;
                int row = cb >> 3;
                int ch  = cb & 7;
                int sw  = ch ^ (row & 7);
                const __half* src = B + (n0 + row) * (size_t)K + kbase + ch * 8;
                cp16(base + 16384u + (uint32_t)(row * 128 + sw * 16), src);
            }
        }
    }
    asm volatile("cp.async.commit_group;" ::: "memory");
}

__global__ __launch_bounds__(256, 2)
void gemm_f16_kernel(const __half* __restrict__ A, const __half* __restrict__ B,
                     const float* __restrict__ bias, float* __restrict__ C,
                     int M, int N, int K, int hasBias)
{
    extern __shared__ __align__(1024) char smem[];
    uint32_t sb = s2u(smem);
    int tid = threadIdx.x, lane = tid & 31, wid = tid >> 5;
    int wm = wid & 3, wn = wid >> 2;               // 4 x 2 warp grid, 32x64 warp tile
    size_t m0 = (size_t)blockIdx.y * GBM;
    size_t n0 = (size_t)blockIdx.x * GBN;
    const int NS = K / GBK;                        // 16

    float acc[2][8][4];
#pragma unroll
    for (int mt = 0; mt < 2; mt++)
#pragma unroll
        for (int nt = 0; nt < 8; nt++)
#pragma unroll
            for (int j = 0; j < 4; j++) acc[mt][nt][j] = 0.f;

    gemm_load_stage(0, 0, NS, sb, A, B, m0, n0, K, tid);
    gemm_load_stage(1, 1, NS, sb, A, B, m0, n0, K, tid);

    int arow_b = wm * 32 + (lane & 15);            // + mt*16
    int achb   = lane >> 4;                        // + 2*ks
    int brow_b = wn * 64 + (lane & 7) + ((lane >> 4) & 1) * 8;   // + np*16
    int bchb   = (lane >> 3) & 1;                  // + 2*ks

    int buf = 0;
    for (int s = 0; s < NS; s++) {
        asm volatile("cp.async.wait_group %0;" :: "n"(NSTAGE - 2));
        __syncthreads();
        int nb = buf + 2; if (nb >= NSTAGE) nb -= NSTAGE;
        gemm_load_stage(nb, s + 2, NS, sb, A, B, m0, n0, K, tid);
        uint32_t st = sb + (uint32_t)buf * STG;
#pragma unroll
        for (int ks = 0; ks < 4; ks++) {
            uint32_t a[2][4];                       // [mt]
#pragma unroll
            for (int mt = 0; mt < 2; mt++) {
                int row = arow_b + mt * 16;
                int ch = achb + 2 * ks;
                int sw = ch ^ (row & 7);
                LDSM4(a[mt], st + (uint32_t)(row * 128 + sw * 16));
            }
#pragma unroll
            for (int np = 0; np < 4; np++) {
                int row = brow_b + np * 16;
                int ch = bchb + 2 * ks;
                int sw = ch ^ (row & 7);
                uint32_t b[4];
                LDSM4(b, st + 16384u + (uint32_t)(row * 128 + sw * 16));
#pragma unroll
                for (int mt = 0; mt < 2; mt++) {
#pragma unroll
                    for (int half = 0; half < 2; half++) {
                        MMA_F16(acc[mt][np * 2 + half], a[mt], &b[half * 2]);
                    }
                }
            }
        }
        if (++buf == NSTAGE) buf = 0;
    }

    // epilogue
#pragma unroll
    for (int mt = 0; mt < 2; mt++) {
        size_t row = m0 + wm * 32 + mt * 16 + (lane >> 2);
#pragma unroll
        for (int half = 0; half < 2; half++) {
            float* Cp = C + (row + half * 8) * (size_t)N + n0 + wn * 64 + (lane & 3) * 2;
#pragma unroll
            for (int nt = 0; nt < 8; nt++) {
                float2 v;
                v.x = acc[mt][nt][half * 2];
                v.y = acc[mt][nt][half * 2 + 1];
                if (hasBias) {
                    int col = (int)(n0 + wn * 64 + nt * 8 + (lane & 3) * 2);
                    v.x += __ldg(&bias[col]);
                    v.y += __ldg(&bias[col + 1]);
                }
                *(float2*)(Cp + nt * 8) = v;
            }
        }
    }
}

// ---------------- fast exp (FMA pipe) ----------------
__device__ __forceinline__ float fast_exp(float x) {
    float t = x * 1.4426950408889634f;
    t = fminf(fmaxf(t, -126.f), 126.f);
    float z = t + 12582912.f;
    int i = __float_as_int(z);
    float f = t - (z - 12582912.f);
    float p = 1.5403530e-4f;
    p = fmaf(p, f, 1.3333558e-3f);
    p = fmaf(p, f, 9.6181291e-3f);
    p = fmaf(p, f, 5.5504109e-2f);
    p = fmaf(p, f, 2.4022651e-1f);
    p = fmaf(p, f, 6.9314718e-1f);
    p = fmaf(p, f, 1.0f);
    return __int_as_float(__float_as_int(p) + (i << 23));
}
__device__ __forceinline__ float rcp_approx(float x) {
    float r; asm("rcp.approx.f32 %0, %1;" : "=f"(r) : "f"(x)); return r;
}
__device__ __forceinline__ float sqrt_approx(float x) {
    float r; asm("sqrt.approx.f32 %0, %1;" : "=f"(r) : "f"(x)); return r;
}

// ---------------- gates + within-chunk clamped scan ----------------
__global__ __launch_bounds__(256) void gate_intra_kernel(
    const float* __restrict__ aiv, const float* __restrict__ bias,
    float* __restrict__ intra_out, float* __restrict__ cd_out,
    float* __restrict__ S_out, float* __restrict__ D_out)
{
    int g = blockIdx.x * 256 + threadIdx.x;
    int d = g & (DR - 1);
    int n = (g >> 10) & (NCHUNK - 1);
    int b = g >> 17;

    float bd = bias[d];
    float cd = 1.f, inv_cd = 1.f, wsum = 0.f, intra = 0.f;
    size_t row0 = (size_t)b * SEQ + (size_t)n * CHUNK;

    for (int t = 0; t < CHUNK; t++) {
        size_t row = row0 + t;
        const float* p = aiv + row * DR3;
        float ap  = p[d];
        float ipr = p[d + DR];
        float v   = p[d + 2 * DR];

        float ea = fast_exp(-(ap + bd));
        float ua = 1.f + ea;                 // = 1/a
        float ei = fast_exp(-ipr);
        float ui = 1.f + ei;                 // = 1/i
        float r = rcp_approx(ua * ui);
        float a  = r * ui;
        float ii = r * ua;
        float sig = sqrt_approx(fmaxf(fmaf(-a, a, 1.f), 1e-8f)) * (ii * v);

        cd *= a;
        inv_cd *= ua;
        float w = (cd >= 1e-10f) ? inv_cd : 1e10f;
        wsum = fmaf(sig, w, wsum);
        intra = cd * wsum;

        size_t o = row * DR + d;
        intra_out[o] = intra;
        cd_out[o]    = cd;
    }
    S_out[g] = intra;
    D_out[g] = cd;
}

// ---------------- chunk-level recurrence (reference-exact log/exp path) ----------------
__global__ void chunk_scan_kernel(const float* __restrict__ S, const float* __restrict__ D,
                                  float* __restrict__ inc)
{
    int g = blockIdx.x * blockDim.x + threadIdx.x;
    if (g >= BATCH * DR) return;
    int d = g & (DR - 1);
    int b = g >> 10;

    float cum_log = 0.f, cumW = 0.f;
    float prevP = 1.f, prevW = 0.f;
    size_t base = (size_t)b * NCHUNK * DR + d;

    float Dn = D[base], Sn = S[base];
    for (int n = 0; n < NCHUNK; n++) {
        size_t idx = base + (size_t)n * DR;
        float Dn1 = 0.f, Sn1 = 0.f;
        if (n + 1 < NCHUNK) {                       // prefetch next (MLP=2)
            Dn1 = D[idx + DR];
            Sn1 = S[idx + DR];
        }
        inc[idx] = prevP * prevW;
        cum_log += logf(fmaxf(Dn, 1e-10f));
        float cumP = expf(cum_log);
        cumW += Sn / fmaxf(cumP, 1e-10f);
        prevP = cumP;
        prevW = cumW;
        Dn = Dn1; Sn = Sn1;
    }
}

// ---------------- cross-chunk fixup + fp16 convert of h ----------------
__global__ __launch_bounds__(256) void apply_cross_kernel(
    const float* __restrict__ intra, const float* __restrict__ cd,
    const float* __restrict__ inc,
    __half* __restrict__ hh)
{
    size_t i4 = (size_t)blockIdx.x * 256 + threadIdx.x;
    size_t base = i4 * 4;
    int d = (int)(base & (DR - 1));
    size_t row = base >> 10;
    int t = (int)(row & (SEQ - 1));
    int b = (int)(row >> 13);
    int n = t >> 6;

    float4 iv = ((const float4*)intra)[i4];
    float4 cv = ((const float4*)cd)[i4];
    float4 nv = *(const float4*)(inc + (((size_t)(b * NCHUNK + n)) << 10) + d);

    float h[4];
    h[0] = fmaf(cv.x, nv.x, iv.x);
    h[1] = fmaf(cv.y, nv.y, iv.y);
    h[2] = fmaf(cv.z, nv.z, iv.z);
    h[3] = fmaf(cv.w, nv.w, iv.w);

    ushort4 sh;
    unsigned short* shp = &sh.x;
#pragma unroll
    for (int j = 0; j < 4; j++)
        shp[j] = __half_as_ushort(__float2half_rn(h[j]));
    ((ushort4*)hh)[i4] = sh;
}

// ---------------- convert x to fp16 ----------------
__global__ __launch_bounds__(256) void convert_kernel(const float* __restrict__ x,
                                                      __half* __restrict__ xh)
{
    size_t i = (size_t)blockIdx.x * 256 + threadIdx.x;
    float4 v = ((const float4*)x)[i];
    ushort4 sh;
    sh.x = __half_as_ushort(__float2half_rn(v.x));
    sh.y = __half_as_ushort(__float2half_rn(v.y));
    sh.z = __half_as_ushort(__float2half_rn(v.z));
    sh.w = __half_as_ushort(__float2half_rn(v.w));
    ((ushort4*)xh)[i] = sh;
}

// ---------------- transpose W[K][N] -> [N][K] fp16 ----------------
__global__ void transpose_half_kernel(const float* __restrict__ W,
                                      __half* __restrict__ T, int K, int N)
{
    __shared__ float tile[32][33];
    int n0 = blockIdx.x * 32, k0 = blockIdx.y * 32;
    int tx = threadIdx.x, ty = threadIdx.y;
#pragma unroll
    for (int i = 0; i < 32; i += 8)
        tile[ty + i][tx] = W[(size_t)(k0 + ty + i) * N + n0 + tx];
    __syncthreads();
#pragma unroll
    for (int i = 0; i < 32; i += 8)
        T[(size_t)(n0 + ty + i) * K + k0 + tx] = __float2half_rn(tile[tx][ty + i]);
}

// ---------------- launch ----------------
extern "C" void kernel_launch(void* const* d_in, const int* in_sizes, int n_in,
                              void* d_out, int out_size)
{
    const float* x          = (const float*)d_in[0];
    const float* W_aiv      = (const float*)d_in[1];
    const float* decay_bias = (const float*)d_in[2];
    const float* W_mix      = (const float*)d_in[3];
    const float* b_mix      = (const float*)d_in[4];
    float* out = (float*)d_out;

    char* pool = nullptr;
    cudaGetSymbolAddress((void**)&pool, g_pool);
    float* aiv    = (float*)(pool + OFF_AIV);
    __half* hh    = (__half*)(pool + OFF_HH);
    __half* xh    = (__half*)(pool + OFF_XH);
    float* intra  = (float*)(pool + OFF_INTRA);
    float* cd     = (float*)(pool + OFF_CD);
    float* Sp     = (float*)(pool + OFF_S);
    float* Dp     = (float*)(pool + OFF_D);
    float* incp   = (float*)(pool + OFF_INC);
    __half* wa    = (__half*)(pool + OFF_WA);
    __half* wm    = (__half*)(pool + OFF_WM);

    const int smem_bytes = NSTAGE * (int)STG;   // 98304
    cudaFuncSetAttribute(gemm_f16_kernel,
                         cudaFuncAttributeMaxDynamicSharedMemorySize, smem_bytes);

    // prep fp16 conversions
    convert_kernel<<<(MROWS * DM / 4) / 256, 256>>>(x, xh);
    transpose_half_kernel<<<dim3(DR3 / 32, DM / 32), dim3(32, 8)>>>(W_aiv, wa, DM, DR3);
    transpose_half_kernel<<<dim3(DR / 32, DR / 32), dim3(32, 8)>>>(W_mix, wm, DR, DR);

    // 1. aiv = x @ W_aiv
    gemm_f16_kernel<<<dim3(DR3 / GBN, MROWS / GBM), 256, smem_bytes>>>(
        xh, wa, nullptr, aiv, MROWS, DR3, DM, 0);

    // 2. gates + within-chunk scan
    gate_intra_kernel<<<(BATCH * NCHUNK * DR) / 256, 256>>>(aiv, decay_bias, intra, cd, Sp, Dp);

    // 3. chunk-level recurrence
    chunk_scan_kernel<<<(BATCH * DR + 127) / 128, 128>>>(Sp, Dp, incp);

    // 4. cross-chunk fixup + fp16 convert of h (reuses aiv region)
    apply_cross_kernel<<<(unsigned)((size_t)MROWS * DR / 4 / 256), 256>>>(
        intra, cd, incp, hh);

    // 5. out = h @ W_mix + b_mix
    gemm_f16_kernel<<<dim3(DR / GBN, MROWS / GBM), 256, smem_bytes>>>(
        hh, wm, b_mix, out, MROWS, DR, DR, 1);
}

// round 17
// speedup vs baseline: 2.4934x; 1.0319x over previous
#include <cuda_runtime.h>
#include <cuda_fp16.h>
#include <math.h>
#include <stdint.h>

// ---------------- problem constants ----------------
#define BATCH   4
#define SEQ     8192
#define DM      1024
#define DR      1024
#define DR3     3072
#define CHUNK   64
#define NCHUNK  128
#define MROWS   32768

// ---------------- scratch pool (bytes) ----------------
#define OFF_AIVH  ((size_t)0)            // fp16 [MROWS][DR3] (201 MB)
#define OFF_HH    ((size_t)0)            // fp16 [MROWS][DR] (reuses aivh after gate)
#define OFF_XH    ((size_t)402653184)    // fp16 [MROWS][DM]
#define OFF_INTRA ((size_t)536870912)    // fp32 [MROWS][DR]
#define OFF_CD    ((size_t)671088640)    // fp32 [MROWS][DR]
#define OFF_S     ((size_t)805306368)
#define OFF_D     ((size_t)807403520)
#define OFF_INC   ((size_t)809500672)
#define OFF_WA    ((size_t)811597824)    // fp16 [DR3][DM] transposed
#define OFF_WM    ((size_t)824180736)    // fp16 [DR][DR] transposed
#define POOL_BYTES ((size_t)828375040)

__device__ __align__(1024) char g_pool[POOL_BYTES];

// ---------------- helpers ----------------
__device__ __forceinline__ uint32_t s2u(const void* p) {
    uint32_t a;
    asm("{ .reg .u64 t; cvta.to.shared.u64 t, %1; cvt.u32.u64 %0, t; }" : "=r"(a) : "l"(p));
    return a;
}
__device__ __forceinline__ void cp16(uint32_t dst, const void* src) {
    asm volatile("cp.async.cg.shared.global [%0], [%1], 16;" :: "r"(dst), "l"(src));
}
#define LDSM4(r, addr) \
    asm volatile("ldmatrix.sync.aligned.m8n8.x4.shared.b16 {%0,%1,%2,%3}, [%4];" \
        : "=r"((r)[0]), "=r"((r)[1]), "=r"((r)[2]), "=r"((r)[3]) : "r"(addr))
#define MMA_F16(d, a, b) \
    asm volatile("mma.sync.aligned.m16n8k16.row.col.f32.f16.f16.f32 " \
        "{%0,%1,%2,%3}, {%4,%5,%6,%7}, {%8,%9}, {%0,%1,%2,%3};" \
        : "+f"((d)[0]), "+f"((d)[1]), "+f"((d)[2]), "+f"((d)[3]) \
        : "r"((a)[0]), "r"((a)[1]), "r"((a)[2]), "r"((a)[3]), "r"((b)[0]), "r"((b)[1]))

// ---------------- fp16 1-term GEMM, 128x128 tile, GBK=64, 3 stages, 2 CTAs/SM --
// C[M,N] = A[M,K] @ B^T  (A,B fp16, B stored [N][K] K-contiguous, fp32 accumulate)
// outHalf: write C as fp16 (__half) instead of fp32
#define GBM 128
#define GBN 128
#define GBK 64
#define NSTAGE 3
#define STG 32768u   // A 16K | B 16K

__device__ __forceinline__ void gemm_load_stage(
    int buf, int kt, int NS, uint32_t sb,
    const __half* A, const __half* B,
    size_t m0, size_t n0, int K, int tid)
{
    if (kt < NS) {
        uint32_t base = sb + (uint32_t)buf * STG;
        size_t kbase = (size_t)kt * GBK;
#pragma unroll
        for (int i = 0; i < 8; i++) {
            int c = tid + i * 256;                  // 0..2047, region uniform per i
            if (c < 1024) {                         // A: 128 rows x 8 chunks
                int row = c >> 3;
                int ch  = c & 7;
                int sw  = ch ^ (row & 7);
                const __half* src = A + (m0 + row) * (size_t)K + kbase + ch * 8;
                cp16(base + (uint32_t)(row * 128 + sw * 16), src);
            } else {                                // B: 128 rows x 8 chunks
                int cb  = c - 1024;
                int row = cb >> 3;
                int ch  = cb & 7;
                int sw  = ch ^ (row & 7);
                const __half* src = B + (n0 + row) * (size_t)K + kbase + ch * 8;
                cp16(base + 16384u + (uint32_t)(row * 128 + sw * 16), src);
            }
        }
    }
    asm volatile("cp.async.commit_group;" ::: "memory");
}

__global__ __launch_bounds__(256, 2)
void gemm_f16_kernel(const __half* __restrict__ A, const __half* __restrict__ B,
                     const float* __restrict__ bias, void* __restrict__ Cv,
                     int M, int N, int K, int hasBias, int outHalf)
{
    extern __shared__ __align__(1024) char smem[];
    uint32_t sb = s2u(smem);
    int tid = threadIdx.x, lane = tid & 31, wid = tid >> 5;
    int wm = wid & 3, wn = wid >> 2;               // 4 x 2 warp grid, 32x64 warp tile
    size_t m0 = (size_t)blockIdx.y * GBM;
    size_t n0 = (size_t)blockIdx.x * GBN;
    const int NS = K / GBK;                        // 16

    float acc[2][8][4];
#pragma unroll
    for (int mt = 0; mt < 2; mt++)
#pragma unroll
        for (int nt = 0; nt < 8; nt++)
#pragma unroll
            for (int j = 0; j < 4; j++) acc[mt][nt][j] = 0.f;

    gemm_load_stage(0, 0, NS, sb, A, B, m0, n0, K, tid);
    gemm_load_stage(1, 1, NS, sb, A, B, m0, n0, K, tid);

    int arow_b = wm * 32 + (lane & 15);            // + mt*16
    int achb   = lane >> 4;                        // + 2*ks
    int brow_b = wn * 64 + (lane & 7) + ((lane >> 4) & 1) * 8;   // + np*16
    int bchb   = (lane >> 3) & 1;                  // + 2*ks

    int buf = 0;
    for (int s = 0; s < NS; s++) {
        asm volatile("cp.async.wait_group %0;" :: "n"(NSTAGE - 2));
        __syncthreads();
        int nb = buf + 2; if (nb >= NSTAGE) nb -= NSTAGE;
        gemm_load_stage(nb, s + 2, NS, sb, A, B, m0, n0, K, tid);
        uint32_t st = sb + (uint32_t)buf * STG;
#pragma unroll
        for (int ks = 0; ks < 4; ks++) {
            uint32_t a[2][4];                       // [mt]
#pragma unroll
            for (int mt = 0; mt < 2; mt++) {
                int row = arow_b + mt * 16;
                int ch = achb + 2 * ks;
                int sw = ch ^ (row & 7);
                LDSM4(a[mt], st + (uint32_t)(row * 128 + sw * 16));
            }
#pragma unroll
            for (int np = 0; np < 4; np++) {
                int row = brow_b + np * 16;
                int ch = bchb + 2 * ks;
                int sw = ch ^ (row & 7);
                uint32_t b[4];
                LDSM4(b, st + 16384u + (uint32_t)(row * 128 + sw * 16));
#pragma unroll
                for (int mt = 0; mt < 2; mt++) {
#pragma unroll
                    for (int half = 0; half < 2; half++) {
                        MMA_F16(acc[mt][np * 2 + half], a[mt], &b[half * 2]);
                    }
                }
            }
        }
        if (++buf == NSTAGE) buf = 0;
    }

    // epilogue
#pragma unroll
    for (int mt = 0; mt < 2; mt++) {
        size_t row = m0 + wm * 32 + mt * 16 + (lane >> 2);
#pragma unroll
        for (int half = 0; half < 2; half++) {
            size_t r = row + half * 8;
            int colb = (int)(n0 + wn * 64 + (lane & 3) * 2);
            if (outHalf) {
                __half* Cp = (__half*)Cv + r * (size_t)N + colb;
#pragma unroll
                for (int nt = 0; nt < 8; nt++) {
                    float vx = acc[mt][nt][half * 2];
                    float vy = acc[mt][nt][half * 2 + 1];
                    *(__half2*)(Cp + nt * 8) = __floats2half2_rn(vx, vy);
                }
            } else {
                float* Cp = (float*)Cv + r * (size_t)N + colb;
#pragma unroll
                for (int nt = 0; nt < 8; nt++) {
                    float2 v;
                    v.x = acc[mt][nt][half * 2];
                    v.y = acc[mt][nt][half * 2 + 1];
                    if (hasBias) {
                        int col = colb + nt * 8;
                        v.x += __ldg(&bias[col]);
                        v.y += __ldg(&bias[col + 1]);
                    }
                    *(float2*)(Cp + nt * 8) = v;
                }
            }
        }
    }
}

// ---------------- fast exp (FMA pipe) ----------------
__device__ __forceinline__ float fast_exp(float x) {
    float t = x * 1.4426950408889634f;
    t = fminf(fmaxf(t, -126.f), 126.f);
    float z = t + 12582912.f;
    int i = __float_as_int(z);
    float f = t - (z - 12582912.f);
    float p = 1.5403530e-4f;
    p = fmaf(p, f, 1.3333558e-3f);
    p = fmaf(p, f, 9.6181291e-3f);
    p = fmaf(p, f, 5.5504109e-2f);
    p = fmaf(p, f, 2.4022651e-1f);
    p = fmaf(p, f, 6.9314718e-1f);
    p = fmaf(p, f, 1.0f);
    return __int_as_float(__float_as_int(p) + (i << 23));
}
__device__ __forceinline__ float rcp_approx(float x) {
    float r; asm("rcp.approx.f32 %0, %1;" : "=f"(r) : "f"(x)); return r;
}
__device__ __forceinline__ float sqrt_approx(float x) {
    float r; asm("sqrt.approx.f32 %0, %1;" : "=f"(r) : "f"(x)); return r;
}

// ---------------- gates + within-chunk clamped scan (fp16 aiv input) ----------
__global__ __launch_bounds__(256) void gate_intra_kernel(
    const __half* __restrict__ aiv, const float* __restrict__ bias,
    float* __restrict__ intra_out, float* __restrict__ cd_out,
    float* __restrict__ S_out, float* __restrict__ D_out)
{
    int g = blockIdx.x * 256 + threadIdx.x;
    int d = g & (DR - 1);
    int n = (g >> 10) & (NCHUNK - 1);
    int b = g >> 17;

    float bd = bias[d];
    float cd = 1.f, inv_cd = 1.f, wsum = 0.f, intra = 0.f;
    size_t row0 = (size_t)b * SEQ + (size_t)n * CHUNK;

    for (int t = 0; t < CHUNK; t++) {
        size_t row = row0 + t;
        const __half* p = aiv + row * DR3;
        float ap  = __half2float(p[d]);
        float ipr = __half2float(p[d + DR]);
        float v   = __half2float(p[d + 2 * DR]);

        float ea = fast_exp(-(ap + bd));
        float ua = 1.f + ea;                 // = 1/a
        float ei = fast_exp(-ipr);
        float ui = 1.f + ei;                 // = 1/i
        float r = rcp_approx(ua * ui);
        float a  = r * ui;
        float ii = r * ua;
        float sig = sqrt_approx(fmaxf(fmaf(-a, a, 1.f), 1e-8f)) * (ii * v);

        cd *= a;
        inv_cd *= ua;
        float w = (cd >= 1e-10f) ? inv_cd : 1e10f;
        wsum = fmaf(sig, w, wsum);
        intra = cd * wsum;

        size_t o = row * DR + d;
        intra_out[o] = intra;
        cd_out[o]    = cd;
    }
    S_out[g] = intra;
    D_out[g] = cd;
}

// ---------------- chunk-level recurrence (reference-exact log/exp path) ----------------
__global__ void chunk_scan_kernel(const float* __restrict__ S, const float* __restrict__ D,
                                  float* __restrict__ inc)
{
    int g = blockIdx.x * blockDim.x + threadIdx.x;
    if (g >= BATCH * DR) return;
    int d = g & (DR - 1);
    int b = g >> 10;

    float cum_log = 0.f, cumW = 0.f;
    float prevP = 1.f, prevW = 0.f;
    size_t base = (size_t)b * NCHUNK * DR + d;

    float Dn = D[base], Sn = S[base];
    for (int n = 0; n < NCHUNK; n++) {
        size_t idx = base + (size_t)n * DR;
        float Dn1 = 0.f, Sn1 = 0.f;
        if (n + 1 < NCHUNK) {                       // prefetch next (MLP=2)
            Dn1 = D[idx + DR];
            Sn1 = S[idx + DR];
        }
        inc[idx] = prevP * prevW;
        cum_log += logf(fmaxf(Dn, 1e-10f));
        float cumP = expf(cum_log);
        cumW += Sn / fmaxf(cumP, 1e-10f);
        prevP = cumP;
        prevW = cumW;
        Dn = Dn1; Sn = Sn1;
    }
}

// ---------------- cross-chunk fixup + fp16 convert of h ----------------
__global__ __launch_bounds__(256) void apply_cross_kernel(
    const float* __restrict__ intra, const float* __restrict__ cd,
    const float* __restrict__ inc,
    __half* __restrict__ hh)
{
    size_t i4 = (size_t)blockIdx.x * 256 + threadIdx.x;
    size_t base = i4 * 4;
    int d = (int)(base & (DR - 1));
    size_t row = base >> 10;
    int t = (int)(row & (SEQ - 1));
    int b = (int)(row >> 13);
    int n = t >> 6;

    float4 iv = ((const float4*)intra)[i4];
    float4 cv = ((const float4*)cd)[i4];
    float4 nv = *(const float4*)(inc + (((size_t)(b * NCHUNK + n)) << 10) + d);

    float h[4];
    h[0] = fmaf(cv.x, nv.x, iv.x);
    h[1] = fmaf(cv.y, nv.y, iv.y);
    h[2] = fmaf(cv.z, nv.z, iv.z);
    h[3] = fmaf(cv.w, nv.w, iv.w);

    ushort4 sh;
    unsigned short* shp = &sh.x;
#pragma unroll
    for (int j = 0; j < 4; j++)
        shp[j] = __half_as_ushort(__float2half_rn(h[j]));
    ((ushort4*)hh)[i4] = sh;
}

// ---------------- convert x to fp16 ----------------
__global__ __launch_bounds__(256) void convert_kernel(const float* __restrict__ x,
                                                      __half* __restrict__ xh)
{
    size_t i = (size_t)blockIdx.x * 256 + threadIdx.x;
    float4 v = ((const float4*)x)[i];
    ushort4 sh;
    sh.x = __half_as_ushort(__float2half_rn(v.x));
    sh.y = __half_as_ushort(__float2half_rn(v.y));
    sh.z = __half_as_ushort(__float2half_rn(v.z));
    sh.w = __half_as_ushort(__float2half_rn(v.w));
    ((ushort4*)xh)[i] = sh;
}

// ---------------- transpose W[K][N] -> [N][K] fp16 ----------------
__global__ void transpose_half_kernel(const float* __restrict__ W,
                                      __half* __restrict__ T, int K, int N)
{
    __shared__ float tile[32][33];
    int n0 = blockIdx.x * 32, k0 = blockIdx.y * 32;
    int tx = threadIdx.x, ty = threadIdx.y;
#pragma unroll
    for (int i = 0; i < 32; i += 8)
        tile[ty + i][tx] = W[(size_t)(k0 + ty + i) * N + n0 + tx];
    __syncthreads();
#pragma unroll
    for (int i = 0; i < 32; i += 8)
        T[(size_t)(n0 + ty + i) * K + k0 + tx] = __float2half_rn(tile[tx][ty + i]);
}

// ---------------- launch ----------------
extern "C" void kernel_launch(void* const* d_in, const int* in_sizes, int n_in,
                              void* d_out, int out_size)
{
    const float* x          = (const float*)d_in[0];
    const float* W_aiv      = (const float*)d_in[1];
    const float* decay_bias = (const float*)d_in[2];
    const float* W_mix      = (const float*)d_in[3];
    const float* b_mix      = (const float*)d_in[4];
    float* out = (float*)d_out;

    char* pool = nullptr;
    cudaGetSymbolAddress((void**)&pool, g_pool);
    __half* aivh  = (__half*)(pool + OFF_AIVH);
    __half* hh    = (__half*)(pool + OFF_HH);
    __half* xh    = (__half*)(pool + OFF_XH);
    float* intra  = (float*)(pool + OFF_INTRA);
    float* cd     = (float*)(pool + OFF_CD);
    float* Sp     = (float*)(pool + OFF_S);
    float* Dp     = (float*)(pool + OFF_D);
    float* incp   = (float*)(pool + OFF_INC);
    __half* wa    = (__half*)(pool + OFF_WA);
    __half* wm    = (__half*)(pool + OFF_WM);

    const int smem_bytes = NSTAGE * (int)STG;   // 98304
    cudaFuncSetAttribute(gemm_f16_kernel,
                         cudaFuncAttributeMaxDynamicSharedMemorySize, smem_bytes);

    // prep fp16 conversions
    convert_kernel<<<(MROWS * DM / 4) / 256, 256>>>(x, xh);
    transpose_half_kernel<<<dim3(DR3 / 32, DM / 32), dim3(32, 8)>>>(W_aiv, wa, DM, DR3);
    transpose_half_kernel<<<dim3(DR / 32, DR / 32), dim3(32, 8)>>>(W_mix, wm, DR, DR);

    // 1. aiv = x @ W_aiv  (fp16 output)
    gemm_f16_kernel<<<dim3(DR3 / GBN, MROWS / GBM), 256, smem_bytes>>>(
        xh, wa, nullptr, aivh, MROWS, DR3, DM, 0, 1);

    // 2. gates + within-chunk scan
    gate_intra_kernel<<<(BATCH * NCHUNK * DR) / 256, 256>>>(aivh, decay_bias, intra, cd, Sp, Dp);

    // 3. chunk-level recurrence
    chunk_scan_kernel<<<(BATCH * DR + 127) / 128, 128>>>(Sp, Dp, incp);

    // 4. cross-chunk fixup + fp16 convert of h (reuses aiv region)
    apply_cross_kernel<<<(unsigned)((size_t)MROWS * DR / 4 / 256), 256>>>(
        intra, cd, incp, hh);

    // 5. out = h @ W_mix + b_mix  (fp32 output)
    gemm_f16_kernel<<<dim3(DR / GBN, MROWS / GBM), 256, smem_bytes>>>(
        hh, wm, b_mix, out, MROWS, DR, DR, 1, 0);
}